// round 3
// baseline (speedup 1.0000x reference)
#include <cuda_runtime.h>
#include <cuda_bf16.h>
#include <cstdint>

// ---------------------------------------------------------------------------
// DrugEncoder (angle branch dead). Live pipeline, fused:
//   node_h = node_hidden @ W + b                       (kernel B -> g_proj)
//   agg[d] += (edge_hidden @ W + b)[b]   fused scatter (kernel C, atomic epi)
//   agg[d] += node_h[ab_src[b]]                        (kernel D)
//   h1 = relu(agg @ W1 + b1) ; h = h1 @ W2 + b2        (kernel E, h1 in smem)
//   h = relu(LN(h)) ; node_out = node_h + h ; pool     (kernel E epilogue)
// TF32 mma.sync (RN-converted), fp32 accum.
// ---------------------------------------------------------------------------

#define NA 500000
#define NB 1000000
#define NG 16384
#define HD 128

__device__ float g_proj[(size_t)NA * HD];   // node_h only
__device__ float g_agg[(size_t)NA * HD];
__device__ float g_cnt[NG];

// ---------------------------------------------------------------------------
__device__ __forceinline__ uint32_t f2tf(float x) {
    uint32_t r;
    asm("cvt.rna.tf32.f32 %0, %1;" : "=r"(r) : "f"(x));
    return r;
}

__device__ __forceinline__ void mma_tf32(float* c, const uint32_t* a, const uint32_t* b) {
    asm volatile(
        "mma.sync.aligned.m16n8k8.row.col.f32.tf32.tf32.f32 "
        "{%0,%1,%2,%3}, {%4,%5,%6,%7}, {%8,%9}, {%0,%1,%2,%3};"
        : "+f"(c[0]), "+f"(c[1]), "+f"(c[2]), "+f"(c[3])
        : "r"(a[0]), "r"(a[1]), "r"(a[2]), "r"(a[3]), "r"(b[0]), "r"(b[1]));
}

__device__ __forceinline__ void red2(float* p, float x, float y) {
    asm volatile("red.global.add.v2.f32 [%0], {%1,%2};"
                 :: "l"(p), "f"(x), "f"(y) : "memory");
}

// ---------------------------------------------------------------------------
__global__ void zero_kernel(float4* __restrict__ out4) {
    size_t i = (size_t)blockIdx.x * blockDim.x + threadIdx.x;
    size_t stride = (size_t)gridDim.x * blockDim.x;
    float4 z = make_float4(0.f, 0.f, 0.f, 0.f);
    float4* agg4 = (float4*)g_agg;
    const size_t nagg4 = (size_t)NA * HD / 4;
    for (size_t j = i; j < nagg4; j += stride) agg4[j] = z;
    const size_t nout4 = (size_t)NG * HD / 4;
    for (size_t j = i; j < nout4; j += stride) out4[j] = z;
    float4* cnt4 = (float4*)g_cnt;
    for (size_t j = i; j < NG / 4; j += stride) cnt4[j] = z;
}

// ---------------------------------------------------------------------------
// Kernel B: node projection. Y = X @ W + b.  Block 128x128, 8 warps 4m x 2n.
// ---------------------------------------------------------------------------
__global__ __launch_bounds__(256) void proj_node_kernel(
    const float* __restrict__ X, const float* __restrict__ W,
    const float* __restrict__ bias, float* __restrict__ Y, int nrows)
{
    __shared__ uint32_t As[128][36];
    __shared__ uint32_t Ws[32][132];

    const int t = threadIdx.x, lane = t & 31, wid = t >> 5;
    const int wm = wid & 3, wn = wid >> 2;
    const int rowbase = blockIdx.x * 128;

    float c[2][8][4];
#pragma unroll
    for (int i = 0; i < 2; i++)
#pragma unroll
        for (int j = 0; j < 8; j++)
#pragma unroll
            for (int k = 0; k < 4; k++) c[i][j][k] = 0.f;

    for (int kt = 0; kt < 128; kt += 32) {
#pragma unroll
        for (int p = 0; p < 4; p++) {
            int idx4 = t + p * 256;
            int r = idx4 >> 5, c4 = idx4 & 31;
            float4 w = *(const float4*)&W[(size_t)(kt + r) * 128 + c4 * 4];
            uint32_t* d = &Ws[r][c4 * 4];
            d[0] = f2tf(w.x); d[1] = f2tf(w.y); d[2] = f2tf(w.z); d[3] = f2tf(w.w);
        }
#pragma unroll
        for (int p = 0; p < 4; p++) {
            int idx4 = t + p * 256;
            int r = idx4 >> 3, c4 = idx4 & 7;
            int gr = rowbase + r;
            float4 v = make_float4(0.f, 0.f, 0.f, 0.f);
            if (gr < nrows) v = *(const float4*)&X[(size_t)gr * 128 + kt + c4 * 4];
            uint32_t* d = &As[r][c4 * 4];
            d[0] = f2tf(v.x); d[1] = f2tf(v.y); d[2] = f2tf(v.z); d[3] = f2tf(v.w);
        }
        __syncthreads();
#pragma unroll
        for (int ks = 0; ks < 4; ks++) {
            const int k0 = ks * 8;
            uint32_t a[2][4], b[8][2];
#pragma unroll
            for (int fm = 0; fm < 2; fm++) {
                int ar = wm * 32 + fm * 16 + (lane >> 2);
                int ac = k0 + (lane & 3);
                a[fm][0] = As[ar][ac];     a[fm][1] = As[ar + 8][ac];
                a[fm][2] = As[ar][ac + 4]; a[fm][3] = As[ar + 8][ac + 4];
            }
#pragma unroll
            for (int fn = 0; fn < 8; fn++) {
                int bc = wn * 64 + fn * 8 + (lane >> 2);
                int br = k0 + (lane & 3);
                b[fn][0] = Ws[br][bc]; b[fn][1] = Ws[br + 4][bc];
            }
#pragma unroll
            for (int fm = 0; fm < 2; fm++)
#pragma unroll
                for (int fn = 0; fn < 8; fn++) mma_tf32(c[fm][fn], a[fm], b[fn]);
        }
        __syncthreads();
    }

#pragma unroll
    for (int fm = 0; fm < 2; fm++) {
        int r0 = rowbase + wm * 32 + fm * 16 + (lane >> 2);
#pragma unroll
        for (int fn = 0; fn < 8; fn++) {
            int col = wn * 64 + fn * 8 + 2 * (lane & 3);
            float bx = bias[col], by = bias[col + 1];
            if (r0 < nrows)
                *(float2*)&Y[(size_t)r0 * 128 + col] =
                    make_float2(c[fm][fn][0] + bx, c[fm][fn][1] + by);
            if (r0 + 8 < nrows)
                *(float2*)&Y[(size_t)(r0 + 8) * 128 + col] =
                    make_float2(c[fm][fn][2] + bx, c[fm][fn][3] + by);
        }
    }
}

// ---------------------------------------------------------------------------
// Kernel C: edge projection fused with scatter: g_agg[ab_dst[row]] += row of
// (edge_hidden @ W + b). Output tile never touches gmem as edge_h.
// ---------------------------------------------------------------------------
__global__ __launch_bounds__(256) void proj_edge_scatter_kernel(
    const float* __restrict__ X, const float* __restrict__ W,
    const float* __restrict__ bias, const int* __restrict__ ab_dst)
{
    __shared__ uint32_t As[128][36];
    __shared__ uint32_t Ws[32][132];

    const int t = threadIdx.x, lane = t & 31, wid = t >> 5;
    const int wm = wid & 3, wn = wid >> 2;
    const int rowbase = blockIdx.x * 128;

    float c[2][8][4];
#pragma unroll
    for (int i = 0; i < 2; i++)
#pragma unroll
        for (int j = 0; j < 8; j++)
#pragma unroll
            for (int k = 0; k < 4; k++) c[i][j][k] = 0.f;

    for (int kt = 0; kt < 128; kt += 32) {
#pragma unroll
        for (int p = 0; p < 4; p++) {
            int idx4 = t + p * 256;
            int r = idx4 >> 5, c4 = idx4 & 31;
            float4 w = *(const float4*)&W[(size_t)(kt + r) * 128 + c4 * 4];
            uint32_t* d = &Ws[r][c4 * 4];
            d[0] = f2tf(w.x); d[1] = f2tf(w.y); d[2] = f2tf(w.z); d[3] = f2tf(w.w);
        }
#pragma unroll
        for (int p = 0; p < 4; p++) {
            int idx4 = t + p * 256;
            int r = idx4 >> 3, c4 = idx4 & 7;
            int gr = rowbase + r;
            float4 v = make_float4(0.f, 0.f, 0.f, 0.f);
            if (gr < NB) v = *(const float4*)&X[(size_t)gr * 128 + kt + c4 * 4];
            uint32_t* d = &As[r][c4 * 4];
            d[0] = f2tf(v.x); d[1] = f2tf(v.y); d[2] = f2tf(v.z); d[3] = f2tf(v.w);
        }
        __syncthreads();
#pragma unroll
        for (int ks = 0; ks < 4; ks++) {
            const int k0 = ks * 8;
            uint32_t a[2][4], b[8][2];
#pragma unroll
            for (int fm = 0; fm < 2; fm++) {
                int ar = wm * 32 + fm * 16 + (lane >> 2);
                int ac = k0 + (lane & 3);
                a[fm][0] = As[ar][ac];     a[fm][1] = As[ar + 8][ac];
                a[fm][2] = As[ar][ac + 4]; a[fm][3] = As[ar + 8][ac + 4];
            }
#pragma unroll
            for (int fn = 0; fn < 8; fn++) {
                int bc = wn * 64 + fn * 8 + (lane >> 2);
                int br = k0 + (lane & 3);
                b[fn][0] = Ws[br][bc]; b[fn][1] = Ws[br + 4][bc];
            }
#pragma unroll
            for (int fm = 0; fm < 2; fm++)
#pragma unroll
                for (int fn = 0; fn < 8; fn++) mma_tf32(c[fm][fn], a[fm], b[fn]);
        }
        __syncthreads();
    }

    // scatter epilogue
#pragma unroll
    for (int fm = 0; fm < 2; fm++) {
        int r0 = rowbase + wm * 32 + fm * 16 + (lane >> 2);
        int r1 = r0 + 8;
        int d0 = (r0 < NB) ? ab_dst[r0] : -1;
        int d1 = (r1 < NB) ? ab_dst[r1] : -1;
#pragma unroll
        for (int fn = 0; fn < 8; fn++) {
            int col = wn * 64 + fn * 8 + 2 * (lane & 3);
            float bx = bias[col], by = bias[col + 1];
            if (d0 >= 0)
                red2(&g_agg[(size_t)d0 * HD + col], c[fm][fn][0] + bx, c[fm][fn][1] + by);
            if (d1 >= 0)
                red2(&g_agg[(size_t)d1 * HD + col], c[fm][fn][2] + bx, c[fm][fn][3] + by);
        }
    }
}

// ---------------------------------------------------------------------------
// Kernel D: agg[ab_dst[b]] += node_h[ab_src[b]]  (warp per bond)
// ---------------------------------------------------------------------------
__global__ __launch_bounds__(256) void gather_scatter_kernel(
    const int* __restrict__ ab_src, const int* __restrict__ ab_dst)
{
    int b = blockIdx.x * 8 + (threadIdx.x >> 5);
    if (b >= NB) return;
    int lane = threadIdx.x & 31;
    int s = ab_src[b];
    int d = ab_dst[b];
    float4 a = *(const float4*)&g_proj[(size_t)s * HD + lane * 4];
    float* dst = &g_agg[(size_t)d * HD + lane * 4];
    asm volatile("red.global.add.v4.f32 [%0], {%1,%2,%3,%4};"
                 :: "l"(dst), "f"(a.x), "f"(a.y), "f"(a.z), "f"(a.w)
                 : "memory");
}

// ---------------------------------------------------------------------------
// Kernel E: fused mlp1 + mlp2 + LN + relu + residual + mean-pool.
// h1 (128x256 tf32) lives in smem; W1/W2 tiles streamed.
// Dynamic smem: As 128x132, Ws 32x132, H1 128x260, red 2x128 float2  ~219.6KB.
// ---------------------------------------------------------------------------
__global__ __launch_bounds__(256) void fused_mlp_kernel(
    const float* __restrict__ X,      // g_agg [NA,128]
    const float* __restrict__ W1, const float* __restrict__ b1,
    const float* __restrict__ W2, const float* __restrict__ b2,
    const float* __restrict__ ln_g, const float* __restrict__ ln_b,
    const int* __restrict__ gid, float* __restrict__ out)
{
    extern __shared__ uint32_t sm[];
    uint32_t* As = sm;                          // [128][132]
    uint32_t* Ws = sm + 128 * 132;              // [32][132]
    uint32_t* H1 = sm + 128 * 132 + 32 * 132;   // [128][260]
    float2* red = (float2*)(H1 + 128 * 260);    // [2][128]

    const int t = threadIdx.x, lane = t & 31, wid = t >> 5;
    const int wm = wid & 3, wn = wid >> 2;
    const int rowbase = blockIdx.x * 128;

    // load full agg tile 128x128 (tf32)
#pragma unroll
    for (int p = 0; p < 16; p++) {
        int idx4 = t + p * 256;
        int r = idx4 >> 5, c4 = idx4 & 31;
        int gr = rowbase + r;
        float4 v = make_float4(0.f, 0.f, 0.f, 0.f);
        if (gr < NA) v = *(const float4*)&X[(size_t)gr * 128 + c4 * 4];
        uint32_t* d = &As[r * 132 + c4 * 4];
        d[0] = f2tf(v.x); d[1] = f2tf(v.y); d[2] = f2tf(v.z); d[3] = f2tf(v.w);
    }

    float c[2][8][4];

    // ---- GEMM1: h1 = relu(agg @ W1 + b1), two 128-col halves ----
    for (int nh = 0; nh < 2; nh++) {
#pragma unroll
        for (int i = 0; i < 2; i++)
#pragma unroll
            for (int j = 0; j < 8; j++)
#pragma unroll
                for (int k = 0; k < 4; k++) c[i][j][k] = 0.f;

        for (int kt = 0; kt < 128; kt += 32) {
            __syncthreads();
#pragma unroll
            for (int p = 0; p < 4; p++) {
                int idx4 = t + p * 256;
                int r = idx4 >> 5, c4 = idx4 & 31;
                float4 w = *(const float4*)&W1[(size_t)(kt + r) * 256 + nh * 128 + c4 * 4];
                uint32_t* d = &Ws[r * 132 + c4 * 4];
                d[0] = f2tf(w.x); d[1] = f2tf(w.y); d[2] = f2tf(w.z); d[3] = f2tf(w.w);
            }
            __syncthreads();
#pragma unroll
            for (int ks = 0; ks < 4; ks++) {
                const int k0 = ks * 8;
                uint32_t a[2][4], b[8][2];
#pragma unroll
                for (int fm = 0; fm < 2; fm++) {
                    int ar = wm * 32 + fm * 16 + (lane >> 2);
                    int ac = kt + k0 + (lane & 3);
                    a[fm][0] = As[ar * 132 + ac];
                    a[fm][1] = As[(ar + 8) * 132 + ac];
                    a[fm][2] = As[ar * 132 + ac + 4];
                    a[fm][3] = As[(ar + 8) * 132 + ac + 4];
                }
#pragma unroll
                for (int fn = 0; fn < 8; fn++) {
                    int bc = wn * 64 + fn * 8 + (lane >> 2);
                    int br = k0 + (lane & 3);
                    b[fn][0] = Ws[br * 132 + bc];
                    b[fn][1] = Ws[(br + 4) * 132 + bc];
                }
#pragma unroll
                for (int fm = 0; fm < 2; fm++)
#pragma unroll
                    for (int fn = 0; fn < 8; fn++) mma_tf32(c[fm][fn], a[fm], b[fn]);
            }
        }
        // bias + relu -> H1 (tf32)
#pragma unroll
        for (int fn = 0; fn < 8; fn++) {
            int col = wn * 64 + fn * 8 + 2 * (lane & 3);
            float bx = b1[nh * 128 + col], by = b1[nh * 128 + col + 1];
#pragma unroll
            for (int fm = 0; fm < 2; fm++) {
                int rl = wm * 32 + fm * 16 + (lane >> 2);
                float v0 = fmaxf(c[fm][fn][0] + bx, 0.f);
                float v1 = fmaxf(c[fm][fn][1] + by, 0.f);
                float v2 = fmaxf(c[fm][fn][2] + bx, 0.f);
                float v3 = fmaxf(c[fm][fn][3] + by, 0.f);
                *(uint2*)&H1[rl * 260 + nh * 128 + col] = make_uint2(f2tf(v0), f2tf(v1));
                *(uint2*)&H1[(rl + 8) * 260 + nh * 128 + col] = make_uint2(f2tf(v2), f2tf(v3));
            }
        }
    }

    // ---- GEMM2: h = h1 @ W2 + b2 ----
#pragma unroll
    for (int i = 0; i < 2; i++)
#pragma unroll
        for (int j = 0; j < 8; j++)
#pragma unroll
            for (int k = 0; k < 4; k++) c[i][j][k] = 0.f;

    for (int kt = 0; kt < 256; kt += 32) {
        __syncthreads();   // also orders H1 writes (first iter) / Ws reuse
#pragma unroll
        for (int p = 0; p < 4; p++) {
            int idx4 = t + p * 256;
            int r = idx4 >> 5, c4 = idx4 & 31;
            float4 w = *(const float4*)&W2[(size_t)(kt + r) * 128 + c4 * 4];
            uint32_t* d = &Ws[r * 132 + c4 * 4];
            d[0] = f2tf(w.x); d[1] = f2tf(w.y); d[2] = f2tf(w.z); d[3] = f2tf(w.w);
        }
        __syncthreads();
#pragma unroll
        for (int ks = 0; ks < 4; ks++) {
            const int k0 = ks * 8;
            uint32_t a[2][4], b[8][2];
#pragma unroll
            for (int fm = 0; fm < 2; fm++) {
                int ar = wm * 32 + fm * 16 + (lane >> 2);
                int ac = kt + k0 + (lane & 3);
                a[fm][0] = H1[ar * 260 + ac];
                a[fm][1] = H1[(ar + 8) * 260 + ac];
                a[fm][2] = H1[ar * 260 + ac + 4];
                a[fm][3] = H1[(ar + 8) * 260 + ac + 4];
            }
#pragma unroll
            for (int fn = 0; fn < 8; fn++) {
                int bc = wn * 64 + fn * 8 + (lane >> 2);
                int br = k0 + (lane & 3);
                b[fn][0] = Ws[br * 132 + bc];
                b[fn][1] = Ws[(br + 4) * 132 + bc];
            }
#pragma unroll
            for (int fm = 0; fm < 2; fm++)
#pragma unroll
                for (int fn = 0; fn < 8; fn++) mma_tf32(c[fm][fn], a[fm], b[fn]);
        }
    }

    // ---- epilogue: bias, LN stats, relu(LN)+residual, pool ----
#pragma unroll
    for (int fn = 0; fn < 8; fn++) {
        int col = wn * 64 + fn * 8 + 2 * (lane & 3);
        float bx = b2[col], by = b2[col + 1];
#pragma unroll
        for (int fm = 0; fm < 2; fm++) {
            c[fm][fn][0] += bx; c[fm][fn][1] += by;
            c[fm][fn][2] += bx; c[fm][fn][3] += by;
        }
    }
    __syncthreads();   // before reusing smem region for red (distinct, but order writes)
#pragma unroll
    for (int fm = 0; fm < 2; fm++) {
#pragma unroll
        for (int h = 0; h < 2; h++) {
            int row_local = wm * 32 + fm * 16 + (lane >> 2) + h * 8;
            float s = 0.f, q = 0.f;
#pragma unroll
            for (int fn = 0; fn < 8; fn++) {
                float v0 = c[fm][fn][2 * h + 0];
                float v1 = c[fm][fn][2 * h + 1];
                s += v0 + v1;
                q += v0 * v0 + v1 * v1;
            }
            s += __shfl_xor_sync(0xffffffffu, s, 1);
            q += __shfl_xor_sync(0xffffffffu, q, 1);
            s += __shfl_xor_sync(0xffffffffu, s, 2);
            q += __shfl_xor_sync(0xffffffffu, q, 2);
            if ((lane & 3) == 0) red[wn * 128 + row_local] = make_float2(s, q);
        }
    }
    __syncthreads();

#pragma unroll
    for (int fm = 0; fm < 2; fm++) {
#pragma unroll
        for (int h = 0; h < 2; h++) {
            int row_local = wm * 32 + fm * 16 + (lane >> 2) + h * 8;
            int gr = rowbase + row_local;
            if (gr >= NA) continue;
            float2 p0 = red[row_local];
            float2 p1 = red[128 + row_local];
            float mu = (p0.x + p1.x) * (1.f / 128.f);
            float var = (p0.y + p1.y) * (1.f / 128.f) - mu * mu;
            float rstd = rsqrtf(var + 1e-5f);
            int g = gid[gr];
#pragma unroll
            for (int fn = 0; fn < 8; fn++) {
                int col = wn * 64 + fn * 8 + 2 * (lane & 3);
                float lg0 = ln_g[col], lg1 = ln_g[col + 1];
                float lb0 = ln_b[col], lb1 = ln_b[col + 1];
                float2 nh = *(const float2*)&g_proj[(size_t)gr * HD + col];
                float v0 = c[fm][fn][2 * h + 0];
                float v1 = c[fm][fn][2 * h + 1];
                float o0 = fmaxf((v0 - mu) * rstd * lg0 + lb0, 0.f) + nh.x;
                float o1 = fmaxf((v1 - mu) * rstd * lg1 + lb1, 0.f) + nh.y;
                red2(&out[(size_t)g * HD + col], o0, o1);
            }
            if ((lane & 3) == 0 && wn == 0) atomicAdd(&g_cnt[g], 1.0f);
        }
    }
}

// ---------------------------------------------------------------------------
__global__ void finalize_kernel(float4* __restrict__ out4) {
    int i = blockIdx.x * blockDim.x + threadIdx.x;
    if (i >= NG * (HD / 4)) return;
    int g = i >> 5;
    float inv = 1.0f / fmaxf(g_cnt[g], 1.0f);
    float4 v = out4[i];
    v.x *= inv; v.y *= inv; v.z *= inv; v.w *= inv;
    out4[i] = v;
}

// ---------------------------------------------------------------------------
extern "C" void kernel_launch(void* const* d_in, const int* in_sizes, int n_in,
                              void* d_out, int out_size)
{
    const float* node_hidden = (const float*)d_in[0];
    const float* edge_hidden = (const float*)d_in[1];
    const float* atom_w = (const float*)d_in[3];
    const float* atom_b = (const float*)d_in[4];
    const float* nmlp_w1 = (const float*)d_in[5];
    const float* nmlp_b1 = (const float*)d_in[6];
    const float* nmlp_w2 = (const float*)d_in[7];
    const float* nmlp_b2 = (const float*)d_in[8];
    const float* n_ln_g = (const float*)d_in[9];
    const float* n_ln_b = (const float*)d_in[10];
    const int* ab_src = (const int*)d_in[17];
    const int* ab_dst = (const int*)d_in[18];
    const int* node_graph_id = (const int*)d_in[21];
    float* out = (float*)d_out;

    float *p_proj, *p_agg;
    cudaGetSymbolAddress((void**)&p_proj, g_proj);
    cudaGetSymbolAddress((void**)&p_agg, g_agg);

    const int SMEM_E = (128 * 132 + 32 * 132 + 128 * 260) * 4 + 2 * 128 * 8;
    cudaFuncSetAttribute(fused_mlp_kernel,
                         cudaFuncAttributeMaxDynamicSharedMemorySize, SMEM_E);

    // 1. zero accumulators + output
    zero_kernel<<<2368, 256>>>((float4*)out);

    // 2. node projection
    proj_node_kernel<<<(NA + 127) / 128, 256>>>(
        node_hidden, atom_w, atom_b, p_proj, NA);

    // 3. edge projection fused with scatter into agg
    proj_edge_scatter_kernel<<<(NB + 127) / 128, 256>>>(
        edge_hidden, atom_w, atom_b, ab_dst);

    // 4. node gather-scatter into agg
    gather_scatter_kernel<<<(NB + 7) / 8, 256>>>(ab_src, ab_dst);

    // 5. fused MLP + LN + relu + residual + pool
    fused_mlp_kernel<<<(NA + 127) / 128, 256, SMEM_E>>>(
        p_agg, nmlp_w1, nmlp_b1, nmlp_w2, nmlp_b2,
        n_ln_g, n_ln_b, node_graph_id, out);

    // 6. per-graph mean
    finalize_kernel<<<(NG * (HD / 4) + 255) / 256, 256>>>((float4*)out);
}

// round 4
// speedup vs baseline: 1.1360x; 1.1360x over previous
#include <cuda_runtime.h>
#include <cstdint>

// ---------------------------------------------------------------------------
// DrugEncoder (angle branch dead). Linearity restructure:
//   S[d]    = sum over bonds b (dst=d) of node_hidden[src[b]] + edge_hidden[b]
//   deg[d]  = number of such bonds
//   agg     = S @ W + 2*deg*b          <-- GEMM commuted past the scatter!
//   node_h  = node_hidden @ W + b      (residual only)
//   h1 = relu(agg @ W1 + b1) ; h = h1 @ W2 + b2
//   h = relu(LN(h)) ; out[g] = mean(node_h + h)
// Weights pre-converted to tf32 once. Scatter runs on a forked stream
// concurrently with the node_h GEMM (independent outputs).
// ---------------------------------------------------------------------------

#define NA 500000
#define NB 1000000
#define NG 16384
#define HD 128

__device__ float g_S[(size_t)NA * HD];
__device__ float g_deg[NA];
__device__ float g_proj[(size_t)NA * HD];
__device__ float g_agg[(size_t)NA * HD];
__device__ float g_h1[(size_t)NA * 256];
__device__ float g_cnt[NG];
__device__ uint32_t g_wA[128 * 128];
__device__ uint32_t g_w1[128 * 256];
__device__ uint32_t g_w2[256 * 128];

// ---------------------------------------------------------------------------
__device__ __forceinline__ uint32_t f2tf(float x) {
    uint32_t r;
    asm("cvt.rna.tf32.f32 %0, %1;" : "=r"(r) : "f"(x));
    return r;
}

__device__ __forceinline__ void mma_tf32(float* c, const uint32_t* a, const uint32_t* b) {
    asm volatile(
        "mma.sync.aligned.m16n8k8.row.col.f32.tf32.tf32.f32 "
        "{%0,%1,%2,%3}, {%4,%5,%6,%7}, {%8,%9}, {%0,%1,%2,%3};"
        : "+f"(c[0]), "+f"(c[1]), "+f"(c[2]), "+f"(c[3])
        : "r"(a[0]), "r"(a[1]), "r"(a[2]), "r"(a[3]), "r"(b[0]), "r"(b[1]));
}

__device__ __forceinline__ void red2(float* p, float x, float y) {
    asm volatile("red.global.add.v2.f32 [%0], {%1,%2};"
                 :: "l"(p), "f"(x), "f"(y) : "memory");
}

// ---------------------------------------------------------------------------
__global__ void prep_weights(const float* __restrict__ wa,
                             const float* __restrict__ w1,
                             const float* __restrict__ w2) {
    int i = blockIdx.x * 256 + threadIdx.x;           // 32768 threads
    if (i < 128 * 128) g_wA[i] = f2tf(wa[i]);
    if (i < 128 * 256) { g_w1[i] = f2tf(w1[i]); g_w2[i] = f2tf(w2[i]); }
}

__global__ void zero_S_deg() {
    size_t i = (size_t)blockIdx.x * blockDim.x + threadIdx.x;
    size_t stride = (size_t)gridDim.x * blockDim.x;
    float4 z = make_float4(0.f, 0.f, 0.f, 0.f);
    float4* s4 = (float4*)g_S;
    for (size_t j = i; j < (size_t)NA * HD / 4; j += stride) s4[j] = z;
    for (size_t j = i; j < NA; j += stride) g_deg[j] = 0.f;
}

__global__ void zero_out(float4* __restrict__ out4) {
    size_t i = (size_t)blockIdx.x * blockDim.x + threadIdx.x;
    size_t stride = (size_t)gridDim.x * blockDim.x;
    float4 z = make_float4(0.f, 0.f, 0.f, 0.f);
    for (size_t j = i; j < (size_t)NG * HD / 4; j += stride) out4[j] = z;
    float4* c4 = (float4*)g_cnt;
    for (size_t j = i; j < NG / 4; j += stride) c4[j] = z;
}

// ---------------------------------------------------------------------------
// Raw-feature scatter: S[dst] += node_hidden[src] + edge_hidden[b]; deg[dst]++
// ---------------------------------------------------------------------------
__global__ __launch_bounds__(256) void scatter_raw(
    const float* __restrict__ nh, const float* __restrict__ eh,
    const int* __restrict__ src, const int* __restrict__ dst)
{
    int b = blockIdx.x * 8 + (threadIdx.x >> 5);
    if (b >= NB) return;
    int lane = threadIdx.x & 31;
    int s = src[b];
    int d = dst[b];
    float4 a = *(const float4*)&nh[(size_t)s * HD + lane * 4];
    float4 e = *(const float4*)&eh[(size_t)b * HD + lane * 4];
    float4 v;
    v.x = a.x + e.x; v.y = a.y + e.y; v.z = a.z + e.z; v.w = a.w + e.w;
    float* p = &g_S[(size_t)d * HD + lane * 4];
    asm volatile("red.global.add.v4.f32 [%0], {%1,%2,%3,%4};"
                 :: "l"(p), "f"(v.x), "f"(v.y), "f"(v.z), "f"(v.w)
                 : "memory");
    if (lane == 0) atomicAdd(&g_deg[d], 1.0f);
}

// ---------------------------------------------------------------------------
// GEMM building blocks. Block tile 128 rows x 128 cols, 8 warps 4m x 2n.
// As: full 128x128 K-chunk, tf32, stride 132. Ws: double-buffered 32x132.
// ---------------------------------------------------------------------------
#define AS_W 132
#define AS_ELEMS (128 * AS_W)
#define WS_ELEMS (32 * AS_W)
#define GEMM_SMEM ((AS_ELEMS + 2 * WS_ELEMS) * 4)

__device__ __forceinline__ void load_As(
    uint32_t* As, const float* __restrict__ X, size_t xld, int xcol0,
    int rowbase, int nrows, int t)
{
#pragma unroll
    for (int p = 0; p < 16; p++) {
        int idx4 = t + p * 256;
        int r = idx4 >> 5, c4 = idx4 & 31;
        int gr = rowbase + r;
        float4 v = make_float4(0.f, 0.f, 0.f, 0.f);
        if (gr < nrows) v = *(const float4*)&X[(size_t)gr * xld + xcol0 + c4 * 4];
        uint32_t* d = &As[r * AS_W + c4 * 4];
        d[0] = f2tf(v.x); d[1] = f2tf(v.y); d[2] = f2tf(v.z); d[3] = f2tf(v.w);
    }
}

// K=128 chunk: 4 ktiles of 32, W streamed (preconverted tf32), reg-prefetch.
__device__ __forceinline__ void mma_chunk(
    const uint32_t* As, uint32_t* Ws, const uint32_t* __restrict__ Wg,
    int wld, int wcol0, int t, int lane, int wm, int wn, float c[2][8][4])
{
    uint4 pf[4];
#pragma unroll
    for (int p = 0; p < 4; p++) {
        int idx4 = t + p * 256;
        int r = idx4 >> 5, c4 = idx4 & 31;
        pf[p] = *(const uint4*)&Wg[(size_t)r * wld + wcol0 + c4 * 4];
    }
#pragma unroll
    for (int p = 0; p < 4; p++) {
        int idx4 = t + p * 256;
        int r = idx4 >> 5, c4 = idx4 & 31;
        *(uint4*)&Ws[r * AS_W + c4 * 4] = pf[p];
    }
    __syncthreads();

#pragma unroll
    for (int kt = 0; kt < 4; kt++) {
        uint32_t* cur = Ws + (kt & 1) * WS_ELEMS;
        if (kt < 3) {
#pragma unroll
            for (int p = 0; p < 4; p++) {
                int idx4 = t + p * 256;
                int r = idx4 >> 5, c4 = idx4 & 31;
                pf[p] = *(const uint4*)&Wg[(size_t)((kt + 1) * 32 + r) * wld + wcol0 + c4 * 4];
            }
        }
#pragma unroll
        for (int ks = 0; ks < 4; ks++) {
            const int k0 = ks * 8;
            uint32_t a[2][4], b[8][2];
#pragma unroll
            for (int fm = 0; fm < 2; fm++) {
                int ar = wm * 32 + fm * 16 + (lane >> 2);
                int ac = kt * 32 + k0 + (lane & 3);
                a[fm][0] = As[ar * AS_W + ac];
                a[fm][1] = As[(ar + 8) * AS_W + ac];
                a[fm][2] = As[ar * AS_W + ac + 4];
                a[fm][3] = As[(ar + 8) * AS_W + ac + 4];
            }
#pragma unroll
            for (int fn = 0; fn < 8; fn++) {
                int bc = wn * 64 + fn * 8 + (lane >> 2);
                int br = k0 + (lane & 3);
                b[fn][0] = cur[br * AS_W + bc];
                b[fn][1] = cur[(br + 4) * AS_W + bc];
            }
#pragma unroll
            for (int fm = 0; fm < 2; fm++)
#pragma unroll
                for (int fn = 0; fn < 8; fn++) mma_tf32(c[fm][fn], a[fm], b[fn]);
        }
        if (kt < 3) {
            uint32_t* nxt = Ws + ((kt + 1) & 1) * WS_ELEMS;
#pragma unroll
            for (int p = 0; p < 4; p++) {
                int idx4 = t + p * 256;
                int r = idx4 >> 5, c4 = idx4 & 31;
                *(uint4*)&nxt[r * AS_W + c4 * 4] = pf[p];
            }
            __syncthreads();
        }
    }
}

#define ZERO_C(c) \
    _Pragma("unroll") for (int i = 0; i < 2; i++) \
    _Pragma("unroll") for (int j = 0; j < 8; j++) \
    _Pragma("unroll") for (int k = 0; k < 4; k++) c[i][j][k] = 0.f;

// ---------------------------------------------------------------------------
// GEMM A: node_h = node_hidden @ wA + b -> g_proj
// ---------------------------------------------------------------------------
__global__ __launch_bounds__(256, 2) void gemm_nodeproj(
    const float* __restrict__ X, const float* __restrict__ bias)
{
    extern __shared__ uint32_t sm[];
    uint32_t* As = sm;
    uint32_t* Ws = sm + AS_ELEMS;
    const int t = threadIdx.x, lane = t & 31, wid = t >> 5;
    const int wm = wid & 3, wn = wid >> 2;
    const int rowbase = blockIdx.x * 128;

    float c[2][8][4];
    ZERO_C(c);
    load_As(As, X, 128, 0, rowbase, NA, t);
    mma_chunk(As, Ws, g_wA, 128, 0, t, lane, wm, wn, c);

#pragma unroll
    for (int fm = 0; fm < 2; fm++) {
        int r0 = rowbase + wm * 32 + fm * 16 + (lane >> 2);
#pragma unroll
        for (int fn = 0; fn < 8; fn++) {
            int col = wn * 64 + fn * 8 + 2 * (lane & 3);
            float bx = bias[col], by = bias[col + 1];
            if (r0 < NA)
                *(float2*)&g_proj[(size_t)r0 * HD + col] =
                    make_float2(c[fm][fn][0] + bx, c[fm][fn][1] + by);
            if (r0 + 8 < NA)
                *(float2*)&g_proj[(size_t)(r0 + 8) * HD + col] =
                    make_float2(c[fm][fn][2] + bx, c[fm][fn][3] + by);
        }
    }
}

// ---------------------------------------------------------------------------
// GEMM B: agg = S @ wA + 2*deg*b -> g_agg
// ---------------------------------------------------------------------------
__global__ __launch_bounds__(256, 2) void gemm_agg(
    const float* __restrict__ bias)
{
    extern __shared__ uint32_t sm[];
    uint32_t* As = sm;
    uint32_t* Ws = sm + AS_ELEMS;
    const int t = threadIdx.x, lane = t & 31, wid = t >> 5;
    const int wm = wid & 3, wn = wid >> 2;
    const int rowbase = blockIdx.x * 128;

    float c[2][8][4];
    ZERO_C(c);
    load_As(As, g_S, 128, 0, rowbase, NA, t);
    mma_chunk(As, Ws, g_wA, 128, 0, t, lane, wm, wn, c);

#pragma unroll
    for (int fm = 0; fm < 2; fm++) {
        int r0 = rowbase + wm * 32 + fm * 16 + (lane >> 2);
        float d0 = (r0 < NA) ? 2.f * g_deg[r0] : 0.f;
        float d1 = (r0 + 8 < NA) ? 2.f * g_deg[r0 + 8] : 0.f;
#pragma unroll
        for (int fn = 0; fn < 8; fn++) {
            int col = wn * 64 + fn * 8 + 2 * (lane & 3);
            float bx = bias[col], by = bias[col + 1];
            if (r0 < NA)
                *(float2*)&g_agg[(size_t)r0 * HD + col] =
                    make_float2(c[fm][fn][0] + d0 * bx, c[fm][fn][1] + d0 * by);
            if (r0 + 8 < NA)
                *(float2*)&g_agg[(size_t)(r0 + 8) * HD + col] =
                    make_float2(c[fm][fn][2] + d1 * bx, c[fm][fn][3] + d1 * by);
        }
    }
}

// ---------------------------------------------------------------------------
// GEMM C: h1 = relu(agg @ w1 + b1) -> g_h1  (N=256 via grid.y)
// ---------------------------------------------------------------------------
__global__ __launch_bounds__(256, 2) void gemm_mlp1(
    const float* __restrict__ bias)
{
    extern __shared__ uint32_t sm[];
    uint32_t* As = sm;
    uint32_t* Ws = sm + AS_ELEMS;
    const int t = threadIdx.x, lane = t & 31, wid = t >> 5;
    const int wm = wid & 3, wn = wid >> 2;
    const int rowbase = blockIdx.x * 128;
    const int colbase = blockIdx.y * 128;

    float c[2][8][4];
    ZERO_C(c);
    load_As(As, g_agg, 128, 0, rowbase, NA, t);
    mma_chunk(As, Ws, g_w1, 256, colbase, t, lane, wm, wn, c);

#pragma unroll
    for (int fm = 0; fm < 2; fm++) {
        int r0 = rowbase + wm * 32 + fm * 16 + (lane >> 2);
#pragma unroll
        for (int fn = 0; fn < 8; fn++) {
            int col = colbase + wn * 64 + fn * 8 + 2 * (lane & 3);
            float bx = bias[col], by = bias[col + 1];
            if (r0 < NA)
                *(float2*)&g_h1[(size_t)r0 * 256 + col] =
                    make_float2(fmaxf(c[fm][fn][0] + bx, 0.f),
                                fmaxf(c[fm][fn][1] + by, 0.f));
            if (r0 + 8 < NA)
                *(float2*)&g_h1[(size_t)(r0 + 8) * 256 + col] =
                    make_float2(fmaxf(c[fm][fn][2] + bx, 0.f),
                                fmaxf(c[fm][fn][3] + by, 0.f));
        }
    }
}

// ---------------------------------------------------------------------------
// GEMM D: h = h1 @ w2 + b2 (K=256, two chunks); relu(LN(h)) + residual + pool
// ---------------------------------------------------------------------------
__global__ __launch_bounds__(256, 2) void gemm_mlp2_pool(
    const float* __restrict__ bias,
    const float* __restrict__ ln_g, const float* __restrict__ ln_b,
    const int* __restrict__ gid, float* __restrict__ out)
{
    extern __shared__ uint32_t sm[];
    uint32_t* As = sm;
    uint32_t* Ws = sm + AS_ELEMS;
    float2* red = (float2*)Ws;            // reused after mainloop
    const int t = threadIdx.x, lane = t & 31, wid = t >> 5;
    const int wm = wid & 3, wn = wid >> 2;
    const int rowbase = blockIdx.x * 128;

    float c[2][8][4];
    ZERO_C(c);
#pragma unroll
    for (int kc = 0; kc < 2; kc++) {
        __syncthreads();                   // protect As reuse
        load_As(As, g_h1, 256, kc * 128, rowbase, NA, t);
        mma_chunk(As, Ws, g_w2 + (size_t)kc * 128 * 128, 128, 0,
                  t, lane, wm, wn, c);
    }

    // bias
#pragma unroll
    for (int fn = 0; fn < 8; fn++) {
        int col = wn * 64 + fn * 8 + 2 * (lane & 3);
        float bx = bias[col], by = bias[col + 1];
#pragma unroll
        for (int fm = 0; fm < 2; fm++) {
            c[fm][fn][0] += bx; c[fm][fn][1] += by;
            c[fm][fn][2] += bx; c[fm][fn][3] += by;
        }
    }
    __syncthreads();                       // before reusing Ws as red
    // LN row stats
#pragma unroll
    for (int fm = 0; fm < 2; fm++) {
#pragma unroll
        for (int h = 0; h < 2; h++) {
            int row_local = wm * 32 + fm * 16 + (lane >> 2) + h * 8;
            float s = 0.f, q = 0.f;
#pragma unroll
            for (int fn = 0; fn < 8; fn++) {
                float v0 = c[fm][fn][2 * h + 0];
                float v1 = c[fm][fn][2 * h + 1];
                s += v0 + v1;
                q += v0 * v0 + v1 * v1;
            }
            s += __shfl_xor_sync(0xffffffffu, s, 1);
            q += __shfl_xor_sync(0xffffffffu, q, 1);
            s += __shfl_xor_sync(0xffffffffu, s, 2);
            q += __shfl_xor_sync(0xffffffffu, q, 2);
            if ((lane & 3) == 0) red[wn * 128 + row_local] = make_float2(s, q);
        }
    }
    __syncthreads();

#pragma unroll
    for (int fm = 0; fm < 2; fm++) {
#pragma unroll
        for (int h = 0; h < 2; h++) {
            int row_local = wm * 32 + fm * 16 + (lane >> 2) + h * 8;
            int gr = rowbase + row_local;
            if (gr >= NA) continue;
            float2 p0 = red[row_local];
            float2 p1 = red[128 + row_local];
            float mu = (p0.x + p1.x) * (1.f / 128.f);
            float var = (p0.y + p1.y) * (1.f / 128.f) - mu * mu;
            float rstd = rsqrtf(var + 1e-5f);
            int g = gid[gr];
#pragma unroll
            for (int fn = 0; fn < 8; fn++) {
                int col = wn * 64 + fn * 8 + 2 * (lane & 3);
                float lg0 = ln_g[col], lg1 = ln_g[col + 1];
                float lb0 = ln_b[col], lb1 = ln_b[col + 1];
                float2 nh = *(const float2*)&g_proj[(size_t)gr * HD + col];
                float v0 = c[fm][fn][2 * h + 0];
                float v1 = c[fm][fn][2 * h + 1];
                float o0 = fmaxf((v0 - mu) * rstd * lg0 + lb0, 0.f) + nh.x;
                float o1 = fmaxf((v1 - mu) * rstd * lg1 + lb1, 0.f) + nh.y;
                red2(&out[(size_t)g * HD + col], o0, o1);
            }
            if ((lane & 3) == 0 && wn == 0) atomicAdd(&g_cnt[g], 1.0f);
        }
    }
}

// ---------------------------------------------------------------------------
__global__ void finalize_kernel(float4* __restrict__ out4) {
    int i = blockIdx.x * blockDim.x + threadIdx.x;
    if (i >= NG * (HD / 4)) return;
    int g = i >> 5;
    float inv = 1.0f / fmaxf(g_cnt[g], 1.0f);
    float4 v = out4[i];
    v.x *= inv; v.y *= inv; v.z *= inv; v.w *= inv;
    out4[i] = v;
}

// ---------------------------------------------------------------------------
extern "C" void kernel_launch(void* const* d_in, const int* in_sizes, int n_in,
                              void* d_out, int out_size)
{
    const float* node_hidden = (const float*)d_in[0];
    const float* edge_hidden = (const float*)d_in[1];
    const float* atom_w = (const float*)d_in[3];
    const float* atom_b = (const float*)d_in[4];
    const float* nmlp_w1 = (const float*)d_in[5];
    const float* nmlp_b1 = (const float*)d_in[6];
    const float* nmlp_w2 = (const float*)d_in[7];
    const float* nmlp_b2 = (const float*)d_in[8];
    const float* n_ln_g = (const float*)d_in[9];
    const float* n_ln_b = (const float*)d_in[10];
    const int* ab_src = (const int*)d_in[17];
    const int* ab_dst = (const int*)d_in[18];
    const int* node_graph_id = (const int*)d_in[21];
    float* out = (float*)d_out;

    static cudaStream_t s2 = nullptr;
    static cudaEvent_t evF = nullptr, evJ = nullptr;
    if (!s2) {
        cudaStreamCreateWithFlags(&s2, cudaStreamNonBlocking);
        cudaEventCreateWithFlags(&evF, cudaEventDisableTiming);
        cudaEventCreateWithFlags(&evJ, cudaEventDisableTiming);
        cudaFuncSetAttribute(gemm_nodeproj,
            cudaFuncAttributeMaxDynamicSharedMemorySize, GEMM_SMEM);
        cudaFuncSetAttribute(gemm_agg,
            cudaFuncAttributeMaxDynamicSharedMemorySize, GEMM_SMEM);
        cudaFuncSetAttribute(gemm_mlp1,
            cudaFuncAttributeMaxDynamicSharedMemorySize, GEMM_SMEM);
        cudaFuncSetAttribute(gemm_mlp2_pool,
            cudaFuncAttributeMaxDynamicSharedMemorySize, GEMM_SMEM);
    }

    const int NBLK = (NA + 127) / 128;

    // fork: scatter leg (DRAM-bound) runs concurrently with node_h GEMM
    cudaEventRecord(evF, 0);
    cudaStreamWaitEvent(s2, evF, 0);
    zero_S_deg<<<2048, 256, 0, s2>>>();
    scatter_raw<<<(NB + 7) / 8, 256, 0, s2>>>(node_hidden, edge_hidden,
                                              ab_src, ab_dst);
    cudaEventRecord(evJ, s2);

    // main leg
    prep_weights<<<128, 256>>>(atom_w, nmlp_w1, nmlp_w2);
    zero_out<<<512, 256>>>((float4*)out);
    gemm_nodeproj<<<NBLK, 256, GEMM_SMEM>>>(node_hidden, atom_b);

    cudaStreamWaitEvent((cudaStream_t)0, evJ, 0);   // join: agg needs S, deg
    gemm_agg<<<NBLK, 256, GEMM_SMEM>>>(atom_b);
    gemm_mlp1<<<dim3(NBLK, 2), 256, GEMM_SMEM>>>(nmlp_b1);
    gemm_mlp2_pool<<<NBLK, 256, GEMM_SMEM>>>(nmlp_b2, n_ln_g, n_ln_b,
                                             node_graph_id, out);
    finalize_kernel<<<(NG * (HD / 4) + 255) / 256, 256>>>((float4*)out);
}

// round 8
// speedup vs baseline: 1.4165x; 1.2469x over previous
#include <cuda_runtime.h>
#include <cuda_fp16.h>
#include <cstdint>

// ---------------------------------------------------------------------------
// DrugEncoder (angle branch dead). Linearity restructure + fp16 mma GEMMs:
//   S[d]   = sum over bonds (node_hidden[src] + edge_hidden[b]) ; deg[d] = count
//   agg    = S @ W + 2*deg*b        (fp16 mma, half2 output)
//   node_h = node_hidden @ W + b    (fp16 mma, fp32 output: residual)
//   h1 = relu(agg @ W1 + b1)        (fp16 mma, half2 output)
//   h  = h1 @ W2 + b2 ; relu(LN(h)) ; +node_h ; mean-pool  (fused epilogue)
// fp16 mantissa == tf32 mantissa (10 bits) -> same rel_err as tf32 path,
// but m16n8k16 issues at 2x the tf32 m16n8k8 rate; half2 intermediates
// halve agg/h1 traffic. tcgen05 unavailable (harness targets sm_103).
// ---------------------------------------------------------------------------

#define NA 500000
#define NB 1000000
#define NG 16384
#define HD 128

__device__ float g_S[(size_t)NA * HD];
__device__ float g_deg[NA];
__device__ float g_proj[(size_t)NA * HD];
__device__ uint32_t g_aggH[(size_t)NA * 64];    // half2 pairs [NA][64]
__device__ uint32_t g_h1H[(size_t)NA * 128];    // half2 pairs [NA][128]
__device__ float g_cnt[NG];
__device__ uint32_t g_wAp[64 * 128];            // packed W pairs [K/2][N]
__device__ uint32_t g_w1p[64 * 256];
__device__ uint32_t g_w2p[128 * 128];

// ---------------------------------------------------------------------------
__device__ __forceinline__ uint32_t packh2(float lo, float hi) {
    __half2 h = __floats2half2_rn(lo, hi);
    return *(uint32_t*)&h;
}

__device__ __forceinline__ void mma_f16(float* c, const uint32_t* a, const uint32_t* b) {
    asm volatile(
        "mma.sync.aligned.m16n8k16.row.col.f32.f16.f16.f32 "
        "{%0,%1,%2,%3}, {%4,%5,%6,%7}, {%8,%9}, {%0,%1,%2,%3};"
        : "+f"(c[0]), "+f"(c[1]), "+f"(c[2]), "+f"(c[3])
        : "r"(a[0]), "r"(a[1]), "r"(a[2]), "r"(a[3]), "r"(b[0]), "r"(b[1]));
}

// smem strides in b32 units (chosen bank-conflict-free for fragment reads)
#define AS_P 68      // 64 pair-cols + pad
#define WS_P 136     // 128 N-cols + pad (8j+i bank pattern)
#define AS_BYTES (128 * AS_P * 4)
#define WS_BYTES (64 * WS_P * 4)
#define SM_GEMM (AS_BYTES + WS_BYTES)

#define ZERO_C(c) \
    _Pragma("unroll") for (int i = 0; i < 2; i++) \
    _Pragma("unroll") for (int j = 0; j < 8; j++) \
    _Pragma("unroll") for (int k = 0; k < 4; k++) c[i][j][k] = 0.f;

// K=128 mainloop: 8 x m16n8k16 steps; 8 warps 4m x 2n, warp tile 32x64.
__device__ __forceinline__ void mma_k128(const uint32_t* As, const uint32_t* Ws,
                                         int lane, int wm, int wn, float c[2][8][4]) {
#pragma unroll
    for (int ks = 0; ks < 8; ks++) {
        const int kp0 = ks * 8;          // pair-index base (16 halfs)
        uint32_t a[2][4], b[8][2];
#pragma unroll
        for (int fm = 0; fm < 2; fm++) {
            int ar = wm * 32 + fm * 16 + (lane >> 2);
            int ac = kp0 + (lane & 3);
            a[fm][0] = As[ar * AS_P + ac];
            a[fm][1] = As[(ar + 8) * AS_P + ac];
            a[fm][2] = As[ar * AS_P + ac + 4];
            a[fm][3] = As[(ar + 8) * AS_P + ac + 4];
        }
#pragma unroll
        for (int fn = 0; fn < 8; fn++) {
            int bc = wn * 64 + fn * 8 + (lane >> 2);
            int br = kp0 + (lane & 3);
            b[fn][0] = Ws[br * WS_P + bc];
            b[fn][1] = Ws[(br + 4) * WS_P + bc];
        }
#pragma unroll
        for (int fm = 0; fm < 2; fm++)
#pragma unroll
            for (int fn = 0; fn < 8; fn++) mma_f16(c[fm][fn], a[fm], b[fn]);
    }
}

// load 128x128 fp32 tile, convert to packed half2 pairs
__device__ __forceinline__ void loadA_f32(uint32_t* As, const float* __restrict__ X,
                                          int xld, int rowbase, int t) {
#pragma unroll
    for (int p = 0; p < 16; p++) {
        int idx4 = t + p * 256;
        int r = idx4 >> 5, c4 = idx4 & 31;
        int gr = rowbase + r;
        float4 v = make_float4(0.f, 0.f, 0.f, 0.f);
        if (gr < NA) v = *(const float4*)&X[(size_t)gr * xld + c4 * 4];
        *(uint2*)&As[r * AS_P + c4 * 2] =
            make_uint2(packh2(v.x, v.y), packh2(v.z, v.w));
    }
}

// load 128-row tile of packed-half2 source (xldp b32 per row, col offset xc0p)
__device__ __forceinline__ void loadA_h(uint32_t* As, const uint32_t* __restrict__ Xh,
                                        int xldp, int xc0p, int rowbase, int t) {
#pragma unroll
    for (int p = 0; p < 8; p++) {
        int idx = t + p * 256;
        int r = idx >> 4, cq = idx & 15;
        int gr = rowbase + r;
        uint4 v = make_uint4(0u, 0u, 0u, 0u);
        if (gr < NA) v = *(const uint4*)&Xh[(size_t)gr * xldp + xc0p + cq * 4];
        *(uint4*)&As[r * AS_P + cq * 4] = v;
    }
}

// load 64x128 packed W tile (row stride wldp b32, col offset wc0)
__device__ __forceinline__ void loadW(uint32_t* Ws, const uint32_t* __restrict__ Wp,
                                      int wldp, int wc0, int t) {
#pragma unroll
    for (int p = 0; p < 8; p++) {
        int idx = t + p * 256;
        int r = idx >> 5, cq = idx & 31;
        *(uint4*)&Ws[r * WS_P + cq * 4] = *(const uint4*)&Wp[(size_t)r * wldp + wc0 + cq * 4];
    }
}

// ---------------------------------------------------------------------------
__global__ void prep_weights(const float* __restrict__ wa,
                             const float* __restrict__ w1,
                             const float* __restrict__ w2) {
    int i = blockIdx.x * 256 + threadIdx.x;            // 32768 threads
    if (i < 64 * 128) {
        int k2 = i >> 7, n = i & 127;
        g_wAp[i] = packh2(wa[(2 * k2) * 128 + n], wa[(2 * k2 + 1) * 128 + n]);
    }
    if (i < 64 * 256) {
        int k2 = i >> 8, n = i & 255;
        g_w1p[i] = packh2(w1[(2 * k2) * 256 + n], w1[(2 * k2 + 1) * 256 + n]);
    }
    if (i < 128 * 128) {
        int k2 = i >> 7, n = i & 127;
        g_w2p[i] = packh2(w2[(2 * k2) * 128 + n], w2[(2 * k2 + 1) * 128 + n]);
    }
}

__global__ void zero_S_deg() {
    size_t i = (size_t)blockIdx.x * blockDim.x + threadIdx.x;
    size_t stride = (size_t)gridDim.x * blockDim.x;
    float4 z = make_float4(0.f, 0.f, 0.f, 0.f);
    float4* s4 = (float4*)g_S;
    for (size_t j = i; j < (size_t)NA * HD / 4; j += stride) s4[j] = z;
    for (size_t j = i; j < NA; j += stride) g_deg[j] = 0.f;
}

__global__ void zero_out(float4* __restrict__ out4) {
    size_t i = (size_t)blockIdx.x * blockDim.x + threadIdx.x;
    size_t stride = (size_t)gridDim.x * blockDim.x;
    float4 z = make_float4(0.f, 0.f, 0.f, 0.f);
    for (size_t j = i; j < (size_t)NG * HD / 4; j += stride) out4[j] = z;
    float4* c4 = (float4*)g_cnt;
    for (size_t j = i; j < NG / 4; j += stride) c4[j] = z;
}

// ---------------------------------------------------------------------------
__global__ __launch_bounds__(256) void scatter_raw(
    const float* __restrict__ nh, const float* __restrict__ eh,
    const int* __restrict__ src, const int* __restrict__ dst)
{
    int b = blockIdx.x * 8 + (threadIdx.x >> 5);
    if (b >= NB) return;
    int lane = threadIdx.x & 31;
    int s = src[b];
    int d = dst[b];
    float4 a = *(const float4*)&nh[(size_t)s * HD + lane * 4];
    float4 e = *(const float4*)&eh[(size_t)b * HD + lane * 4];
    float4 v;
    v.x = a.x + e.x; v.y = a.y + e.y; v.z = a.z + e.z; v.w = a.w + e.w;
    float* p = &g_S[(size_t)d * HD + lane * 4];
    asm volatile("red.global.add.v4.f32 [%0], {%1,%2,%3,%4};"
                 :: "l"(p), "f"(v.x), "f"(v.y), "f"(v.z), "f"(v.w) : "memory");
    if (lane == 0) atomicAdd(&g_deg[d], 1.0f);
}

// ---------------------------------------------------------------------------
// nodeproj: proj = node_hidden @ W + b  (fp32 output: residual precision)
// ---------------------------------------------------------------------------
__global__ __launch_bounds__(256) void gemm_nodeproj(
    const float* __restrict__ X, const float* __restrict__ bias)
{
    extern __shared__ uint32_t sm[];
    uint32_t* As = sm;
    uint32_t* Ws = sm + 128 * AS_P;
    const int t = threadIdx.x, lane = t & 31, wid = t >> 5;
    const int wm = wid & 3, wn = wid >> 2;
    const int rowbase = blockIdx.x * 128;

    float c[2][8][4];
    ZERO_C(c);
    loadA_f32(As, X, 128, rowbase, t);
    loadW(Ws, g_wAp, 128, 0, t);
    __syncthreads();
    mma_k128(As, Ws, lane, wm, wn, c);

#pragma unroll
    for (int fm = 0; fm < 2; fm++) {
        int r0 = rowbase + wm * 32 + fm * 16 + (lane >> 2);
#pragma unroll
        for (int fn = 0; fn < 8; fn++) {
            int col = wn * 64 + fn * 8 + 2 * (lane & 3);
            float bx = bias[col], by = bias[col + 1];
            if (r0 < NA)
                *(float2*)&g_proj[(size_t)r0 * 128 + col] =
                    make_float2(c[fm][fn][0] + bx, c[fm][fn][1] + by);
            if (r0 + 8 < NA)
                *(float2*)&g_proj[(size_t)(r0 + 8) * 128 + col] =
                    make_float2(c[fm][fn][2] + bx, c[fm][fn][3] + by);
        }
    }
}

// ---------------------------------------------------------------------------
// agg: aggH = half2(S @ W + 2*deg*b)
// ---------------------------------------------------------------------------
__global__ __launch_bounds__(256) void gemm_agg(const float* __restrict__ bias)
{
    extern __shared__ uint32_t sm[];
    uint32_t* As = sm;
    uint32_t* Ws = sm + 128 * AS_P;
    const int t = threadIdx.x, lane = t & 31, wid = t >> 5;
    const int wm = wid & 3, wn = wid >> 2;
    const int rowbase = blockIdx.x * 128;

    float c[2][8][4];
    ZERO_C(c);
    loadA_f32(As, g_S, 128, rowbase, t);
    loadW(Ws, g_wAp, 128, 0, t);
    __syncthreads();
    mma_k128(As, Ws, lane, wm, wn, c);

#pragma unroll
    for (int fm = 0; fm < 2; fm++) {
        int r0 = rowbase + wm * 32 + fm * 16 + (lane >> 2);
        float d0 = (r0 < NA) ? 2.f * g_deg[r0] : 0.f;
        float d1 = (r0 + 8 < NA) ? 2.f * g_deg[r0 + 8] : 0.f;
#pragma unroll
        for (int fn = 0; fn < 8; fn++) {
            int colp = wn * 32 + fn * 4 + (lane & 3);
            int col = colp * 2;
            float bx = bias[col], by = bias[col + 1];
            if (r0 < NA)
                g_aggH[(size_t)r0 * 64 + colp] =
                    packh2(c[fm][fn][0] + d0 * bx, c[fm][fn][1] + d0 * by);
            if (r0 + 8 < NA)
                g_aggH[(size_t)(r0 + 8) * 64 + colp] =
                    packh2(c[fm][fn][2] + d1 * bx, c[fm][fn][3] + d1 * by);
        }
    }
}

// ---------------------------------------------------------------------------
// mlp1: h1 = relu(agg @ W1 + b1), N=256 via grid.y
// ---------------------------------------------------------------------------
__global__ __launch_bounds__(256) void gemm_mlp1(const float* __restrict__ bias)
{
    extern __shared__ uint32_t sm[];
    uint32_t* As = sm;
    uint32_t* Ws = sm + 128 * AS_P;
    const int t = threadIdx.x, lane = t & 31, wid = t >> 5;
    const int wm = wid & 3, wn = wid >> 2;
    const int rowbase = blockIdx.x * 128;
    const int colbase = blockIdx.y * 128;

    float c[2][8][4];
    ZERO_C(c);
    loadA_h(As, g_aggH, 64, 0, rowbase, t);
    loadW(Ws, g_w1p, 256, colbase, t);
    __syncthreads();
    mma_k128(As, Ws, lane, wm, wn, c);

#pragma unroll
    for (int fm = 0; fm < 2; fm++) {
        int r0 = rowbase + wm * 32 + fm * 16 + (lane >> 2);
#pragma unroll
        for (int fn = 0; fn < 8; fn++) {
            int colp = wn * 32 + fn * 4 + (lane & 3);
            int col = colbase + colp * 2;
            float bx = bias[col], by = bias[col + 1];
            int cp = (colbase >> 1) + colp;
            if (r0 < NA)
                g_h1H[(size_t)r0 * 128 + cp] =
                    packh2(fmaxf(c[fm][fn][0] + bx, 0.f), fmaxf(c[fm][fn][1] + by, 0.f));
            if (r0 + 8 < NA)
                g_h1H[(size_t)(r0 + 8) * 128 + cp] =
                    packh2(fmaxf(c[fm][fn][2] + bx, 0.f), fmaxf(c[fm][fn][3] + by, 0.f));
        }
    }
}

// ---------------------------------------------------------------------------
// mlp2 fused: h = h1 @ W2 + b2 (K=256, 2 chunks); relu(LN(h)) + residual + pool
// ---------------------------------------------------------------------------
__global__ __launch_bounds__(256) void gemm_mlp2_pool(
    const float* __restrict__ bias,
    const float* __restrict__ ln_g, const float* __restrict__ ln_b,
    const int* __restrict__ gid, float* __restrict__ out)
{
    extern __shared__ uint32_t sm[];
    uint32_t* As = sm;
    uint32_t* Ws = sm + 128 * AS_P;
    float2* red = (float2*)Ws;            // reused after mainloop
    const int t = threadIdx.x, lane = t & 31, wid = t >> 5;
    const int wm = wid & 3, wn = wid >> 2;
    const int rowbase = blockIdx.x * 128;

    float c[2][8][4];
    ZERO_C(c);
#pragma unroll
    for (int kc = 0; kc < 2; kc++) {
        if (kc) __syncthreads();          // protect As/Ws reuse
        loadA_h(As, g_h1H, 128, kc * 64, rowbase, t);
        loadW(Ws, g_w2p + (size_t)kc * 64 * 128, 128, 0, t);
        __syncthreads();
        mma_k128(As, Ws, lane, wm, wn, c);
    }

    // bias into fragments
#pragma unroll
    for (int fn = 0; fn < 8; fn++) {
        int col = wn * 64 + fn * 8 + 2 * (lane & 3);
        float bx = bias[col], by = bias[col + 1];
#pragma unroll
        for (int fm = 0; fm < 2; fm++) {
            c[fm][fn][0] += bx; c[fm][fn][1] += by;
            c[fm][fn][2] += bx; c[fm][fn][3] += by;
        }
    }
    __syncthreads();                      // before reusing Ws as red
    // LN row stats (quad shuffles + cross-warp smem reduce)
#pragma unroll
    for (int fm = 0; fm < 2; fm++) {
#pragma unroll
        for (int h = 0; h < 2; h++) {
            int row_local = wm * 32 + fm * 16 + (lane >> 2) + h * 8;
            float s = 0.f, q = 0.f;
#pragma unroll
            for (int fn = 0; fn < 8; fn++) {
                float v0 = c[fm][fn][2 * h + 0];
                float v1 = c[fm][fn][2 * h + 1];
                s += v0 + v1;
                q += v0 * v0 + v1 * v1;
            }
            s += __shfl_xor_sync(0xffffffffu, s, 1);
            q += __shfl_xor_sync(0xffffffffu, q, 1);
            s += __shfl_xor_sync(0xffffffffu, s, 2);
            q += __shfl_xor_sync(0xffffffffu, q, 2);
            if ((lane & 3) == 0) red[wn * 128 + row_local] = make_float2(s, q);
        }
    }
    __syncthreads();

#pragma unroll
    for (int fm = 0; fm < 2; fm++) {
#pragma unroll
        for (int h = 0; h < 2; h++) {
            int row_local = wm * 32 + fm * 16 + (lane >> 2) + h * 8;
            int gr = rowbase + row_local;
            if (gr >= NA) continue;
            float2 p0 = red[row_local];
            float2 p1 = red[128 + row_local];
            float mu = (p0.x + p1.x) * (1.f / 128.f);
            float var = (p0.y + p1.y) * (1.f / 128.f) - mu * mu;
            float rstd = rsqrtf(var + 1e-5f);
            int g = gid[gr];
#pragma unroll
            for (int fn = 0; fn < 8; fn++) {
                int col = wn * 64 + fn * 8 + 2 * (lane & 3);
                float lg0 = ln_g[col], lg1 = ln_g[col + 1];
                float lb0 = ln_b[col], lb1 = ln_b[col + 1];
                float2 nh = *(const float2*)&g_proj[(size_t)gr * HD + col];
                float v0 = c[fm][fn][2 * h + 0];
                float v1 = c[fm][fn][2 * h + 1];
                float o0 = fmaxf((v0 - mu) * rstd * lg0 + lb0, 0.f) + nh.x;
                float o1 = fmaxf((v1 - mu) * rstd * lg1 + lb1, 0.f) + nh.y;
                float* p = &out[(size_t)g * HD + col];
                asm volatile("red.global.add.v2.f32 [%0], {%1,%2};"
                             :: "l"(p), "f"(o0), "f"(o1) : "memory");
            }
            if ((lane & 3) == 0 && wn == 0) atomicAdd(&g_cnt[g], 1.0f);
        }
    }
}

// ---------------------------------------------------------------------------
__global__ void finalize_kernel(float4* __restrict__ out4) {
    int i = blockIdx.x * blockDim.x + threadIdx.x;
    if (i >= NG * (HD / 4)) return;
    int g = i >> 5;
    float inv = 1.0f / fmaxf(g_cnt[g], 1.0f);
    float4 v = out4[i];
    v.x *= inv; v.y *= inv; v.z *= inv; v.w *= inv;
    out4[i] = v;
}

// ---------------------------------------------------------------------------
extern "C" void kernel_launch(void* const* d_in, const int* in_sizes, int n_in,
                              void* d_out, int out_size)
{
    const float* node_hidden = (const float*)d_in[0];
    const float* edge_hidden = (const float*)d_in[1];
    const float* atom_w = (const float*)d_in[3];
    const float* atom_b = (const float*)d_in[4];
    const float* nmlp_w1 = (const float*)d_in[5];
    const float* nmlp_b1 = (const float*)d_in[6];
    const float* nmlp_w2 = (const float*)d_in[7];
    const float* nmlp_b2 = (const float*)d_in[8];
    const float* n_ln_g = (const float*)d_in[9];
    const float* n_ln_b = (const float*)d_in[10];
    const int* ab_src = (const int*)d_in[17];
    const int* ab_dst = (const int*)d_in[18];
    const int* node_graph_id = (const int*)d_in[21];
    float* out = (float*)d_out;

    static cudaStream_t s2 = nullptr;
    static cudaEvent_t evF = nullptr, evJ = nullptr;
    if (!s2) {
        cudaStreamCreateWithFlags(&s2, cudaStreamNonBlocking);
        cudaEventCreateWithFlags(&evF, cudaEventDisableTiming);
        cudaEventCreateWithFlags(&evJ, cudaEventDisableTiming);
        cudaFuncSetAttribute(gemm_nodeproj,
            cudaFuncAttributeMaxDynamicSharedMemorySize, SM_GEMM);
        cudaFuncSetAttribute(gemm_agg,
            cudaFuncAttributeMaxDynamicSharedMemorySize, SM_GEMM);
        cudaFuncSetAttribute(gemm_mlp1,
            cudaFuncAttributeMaxDynamicSharedMemorySize, SM_GEMM);
        cudaFuncSetAttribute(gemm_mlp2_pool,
            cudaFuncAttributeMaxDynamicSharedMemorySize, SM_GEMM);
    }

    const int NBLK = (NA + 127) / 128;

    // fork: raw-feature scatter leg runs concurrently with prep + nodeproj
    cudaEventRecord(evF, 0);
    cudaStreamWaitEvent(s2, evF, 0);
    zero_S_deg<<<2048, 256, 0, s2>>>();
    scatter_raw<<<(NB + 7) / 8, 256, 0, s2>>>(node_hidden, edge_hidden,
                                              ab_src, ab_dst);
    cudaEventRecord(evJ, s2);

    // main leg
    prep_weights<<<128, 256>>>(atom_w, nmlp_w1, nmlp_w2);
    zero_out<<<512, 256>>>((float4*)out);
    gemm_nodeproj<<<NBLK, 256, SM_GEMM>>>(node_hidden, atom_b);

    cudaStreamWaitEvent((cudaStream_t)0, evJ, 0);   // join: agg needs S, deg
    gemm_agg<<<NBLK, 256, SM_GEMM>>>(atom_b);
    gemm_mlp1<<<dim3(NBLK, 2), 256, SM_GEMM>>>(nmlp_b1);
    gemm_mlp2_pool<<<NBLK, 256, SM_GEMM>>>(nmlp_b2, n_ln_g, n_ln_b,
                                           node_graph_id, out);
    finalize_kernel<<<(NG * (HD / 4) + 255) / 256, 256>>>((float4*)out);
}

// round 9
// speedup vs baseline: 1.9358x; 1.3665x over previous
#include <cuda_runtime.h>
#include <cuda_fp16.h>
#include <cstdint>

// ---------------------------------------------------------------------------
// DrugEncoder (angle branch dead). Full linearity restructure:
//   S[d]  = sum over bonds (node_hidden[src]+edge_hidden[b]) ; deg[d] = count
//   P[g]  = sum over atoms in g of node_hidden ; cnt[g] = atom count
//   h1    = relu(S @ Wc + 2*deg*bc + b1)   where Wc = W@W1, bc = b@W1
//   h     = h1 @ W2 + b2 ; hp[g] += relu(LN(h))      (pool atomics)
//   out[g]= (hp[g] + P[g]@W + cnt*b) / max(cnt,1)    (tiny 16384-row GEMM)
// nodeproj and agg GEMMs eliminated by commuting linear ops past pooling/MLP.
// fp16 mma m16n8k16 (mantissa == tf32). tcgen05 unavailable (sm_103 target).
// ---------------------------------------------------------------------------

#define NA 500000
#define NB 1000000
#define NG 16384
#define HD 128

__device__ float g_S[(size_t)NA * HD];
__device__ float g_deg[NA];
__device__ float g_P[(size_t)NG * HD];
__device__ float g_cnt[NG];
__device__ uint32_t g_h1H[(size_t)NA * 128];    // half2 pairs [NA][128]
__device__ uint32_t g_wAp[64 * 128];            // W packed pairs [K/2][N]
__device__ uint32_t g_wcp[64 * 256];            // Wc = W@W1 packed [K/2][256]
__device__ uint32_t g_w2p[128 * 128];           // W2 packed [K/2][128]
__device__ float g_bc[256];                     // b @ W1

// ---------------------------------------------------------------------------
__device__ __forceinline__ uint32_t packh2(float lo, float hi) {
    __half2 h = __floats2half2_rn(lo, hi);
    return *(uint32_t*)&h;
}

__device__ __forceinline__ void mma_f16(float* c, const uint32_t* a, const uint32_t* b) {
    asm volatile(
        "mma.sync.aligned.m16n8k16.row.col.f32.f16.f16.f32 "
        "{%0,%1,%2,%3}, {%4,%5,%6,%7}, {%8,%9}, {%0,%1,%2,%3};"
        : "+f"(c[0]), "+f"(c[1]), "+f"(c[2]), "+f"(c[3])
        : "r"(a[0]), "r"(a[1]), "r"(a[2]), "r"(a[3]), "r"(b[0]), "r"(b[1]));
}

#define AS_P 68
#define WS_P 136
#define SM_GEMM ((128 * AS_P + 64 * WS_P) * 4)

#define ZERO_C(c) \
    _Pragma("unroll") for (int i = 0; i < 2; i++) \
    _Pragma("unroll") for (int j = 0; j < 8; j++) \
    _Pragma("unroll") for (int k = 0; k < 4; k++) c[i][j][k] = 0.f;

// K=128 mainloop: 8 x m16n8k16; 8 warps 4m x 2n, warp tile 32x64.
__device__ __forceinline__ void mma_k128(const uint32_t* As, const uint32_t* Ws,
                                         int lane, int wm, int wn, float c[2][8][4]) {
#pragma unroll
    for (int ks = 0; ks < 8; ks++) {
        const int kp0 = ks * 8;
        uint32_t a[2][4], b[8][2];
#pragma unroll
        for (int fm = 0; fm < 2; fm++) {
            int ar = wm * 32 + fm * 16 + (lane >> 2);
            int ac = kp0 + (lane & 3);
            a[fm][0] = As[ar * AS_P + ac];
            a[fm][1] = As[(ar + 8) * AS_P + ac];
            a[fm][2] = As[ar * AS_P + ac + 4];
            a[fm][3] = As[(ar + 8) * AS_P + ac + 4];
        }
#pragma unroll
        for (int fn = 0; fn < 8; fn++) {
            int bc_ = wn * 64 + fn * 8 + (lane >> 2);
            int br = kp0 + (lane & 3);
            b[fn][0] = Ws[br * WS_P + bc_];
            b[fn][1] = Ws[(br + 4) * WS_P + bc_];
        }
#pragma unroll
        for (int fm = 0; fm < 2; fm++)
#pragma unroll
            for (int fn = 0; fn < 8; fn++) mma_f16(c[fm][fn], a[fm], b[fn]);
    }
}

__device__ __forceinline__ void loadA_f32(uint32_t* As, const float* __restrict__ X,
                                          int xld, int rowbase, int nrows, int t) {
#pragma unroll
    for (int p = 0; p < 16; p++) {
        int idx4 = t + p * 256;
        int r = idx4 >> 5, c4 = idx4 & 31;
        int gr = rowbase + r;
        float4 v = make_float4(0.f, 0.f, 0.f, 0.f);
        if (gr < nrows) v = *(const float4*)&X[(size_t)gr * xld + c4 * 4];
        *(uint2*)&As[r * AS_P + c4 * 2] =
            make_uint2(packh2(v.x, v.y), packh2(v.z, v.w));
    }
}

__device__ __forceinline__ void loadA_h(uint32_t* As, const uint32_t* __restrict__ Xh,
                                        int xldp, int xc0p, int rowbase, int t) {
#pragma unroll
    for (int p = 0; p < 8; p++) {
        int idx = t + p * 256;
        int r = idx >> 4, cq = idx & 15;
        int gr = rowbase + r;
        uint4 v = make_uint4(0u, 0u, 0u, 0u);
        if (gr < NA) v = *(const uint4*)&Xh[(size_t)gr * xldp + xc0p + cq * 4];
        *(uint4*)&As[r * AS_P + cq * 4] = v;
    }
}

__device__ __forceinline__ void loadW(uint32_t* Ws, const uint32_t* __restrict__ Wp,
                                      int wldp, int wc0, int t) {
#pragma unroll
    for (int p = 0; p < 8; p++) {
        int idx = t + p * 256;
        int r = idx >> 5, cq = idx & 31;
        *(uint4*)&Ws[r * WS_P + cq * 4] = *(const uint4*)&Wp[(size_t)r * wldp + wc0 + cq * 4];
    }
}

// ---------------------------------------------------------------------------
// prep: pack W and W2; compute Wc = W@W1 (packed) and bc = b@W1.
// ---------------------------------------------------------------------------
__global__ void prep_weights(const float* __restrict__ wa,
                             const float* __restrict__ w1,
                             const float* __restrict__ w2,
                             const float* __restrict__ ab)
{
    int i = blockIdx.x * 256 + threadIdx.x;            // 32768 threads
    if (i < 64 * 128) {
        int k2 = i >> 7, n = i & 127;
        g_wAp[i] = packh2(wa[(2 * k2) * 128 + n], wa[(2 * k2 + 1) * 128 + n]);
    }
    if (i < 128 * 128) {
        int k2 = i >> 7, n = i & 127;
        g_w2p[i] = packh2(w2[(2 * k2) * 128 + n], w2[(2 * k2 + 1) * 128 + n]);
    }
    if (i < 64 * 256) {                                // Wc pairs
        int k2 = i >> 8, n = i & 255;
        float d0 = 0.f, d1 = 0.f;
        const float* r0 = &wa[(2 * k2) * 128];
        const float* r1 = &wa[(2 * k2 + 1) * 128];
#pragma unroll 4
        for (int j = 0; j < 128; j++) {
            float wj = w1[(size_t)j * 256 + n];
            d0 += r0[j] * wj;
            d1 += r1[j] * wj;
        }
        g_wcp[k2 * 256 + n] = packh2(d0, d1);
    }
    if (i < 256) {                                     // bc
        float s = 0.f;
#pragma unroll 4
        for (int j = 0; j < 128; j++) s += ab[j] * w1[(size_t)j * 256 + i];
        g_bc[i] = s;
    }
}

__global__ void zero_S_deg() {
    size_t i = (size_t)blockIdx.x * blockDim.x + threadIdx.x;
    size_t stride = (size_t)gridDim.x * blockDim.x;
    float4 z = make_float4(0.f, 0.f, 0.f, 0.f);
    float4* s4 = (float4*)g_S;
    for (size_t j = i; j < (size_t)NA * HD / 4; j += stride) s4[j] = z;
    for (size_t j = i; j < NA; j += stride) g_deg[j] = 0.f;
}

__global__ void zero_PO(float4* __restrict__ out4) {
    size_t i = (size_t)blockIdx.x * blockDim.x + threadIdx.x;
    size_t stride = (size_t)gridDim.x * blockDim.x;
    float4 z = make_float4(0.f, 0.f, 0.f, 0.f);
    for (size_t j = i; j < (size_t)NG * HD / 4; j += stride) out4[j] = z;
    float4* p4 = (float4*)g_P;
    for (size_t j = i; j < (size_t)NG * HD / 4; j += stride) p4[j] = z;
    float4* c4 = (float4*)g_cnt;
    for (size_t j = i; j < NG / 4; j += stride) c4[j] = z;
}

// ---------------------------------------------------------------------------
__global__ __launch_bounds__(256) void scatter_raw(
    const float* __restrict__ nh, const float* __restrict__ eh,
    const int* __restrict__ src, const int* __restrict__ dst)
{
    int b = blockIdx.x * 8 + (threadIdx.x >> 5);
    if (b >= NB) return;
    int lane = threadIdx.x & 31;
    int s = src[b];
    int d = dst[b];
    float4 a = *(const float4*)&nh[(size_t)s * HD + lane * 4];
    float4 e = *(const float4*)&eh[(size_t)b * HD + lane * 4];
    float4 v;
    v.x = a.x + e.x; v.y = a.y + e.y; v.z = a.z + e.z; v.w = a.w + e.w;
    float* p = &g_S[(size_t)d * HD + lane * 4];
    asm volatile("red.global.add.v4.f32 [%0], {%1,%2,%3,%4};"
                 :: "l"(p), "f"(v.x), "f"(v.y), "f"(v.z), "f"(v.w) : "memory");
    if (lane == 0) atomicAdd(&g_deg[d], 1.0f);
}

// pool raw node features per graph: P[g] += node_hidden[row]; cnt[g] += 1
__global__ __launch_bounds__(256) void pool_node(
    const float* __restrict__ nh, const int* __restrict__ gid)
{
    int r = blockIdx.x * 8 + (threadIdx.x >> 5);
    if (r >= NA) return;
    int lane = threadIdx.x & 31;
    int g = gid[r];
    float4 v = *(const float4*)&nh[(size_t)r * HD + lane * 4];
    float* p = &g_P[(size_t)g * HD + lane * 4];
    asm volatile("red.global.add.v4.f32 [%0], {%1,%2,%3,%4};"
                 :: "l"(p), "f"(v.x), "f"(v.y), "f"(v.z), "f"(v.w) : "memory");
    if (lane == 0) atomicAdd(&g_cnt[g], 1.0f);
}

// ---------------------------------------------------------------------------
// mlp1': h1 = relu(S @ Wc + 2*deg*bc + b1), N=256 via grid.y
// ---------------------------------------------------------------------------
__global__ __launch_bounds__(256) void gemm_mlp1(const float* __restrict__ bias)
{
    extern __shared__ uint32_t sm[];
    uint32_t* As = sm;
    uint32_t* Ws = sm + 128 * AS_P;
    const int t = threadIdx.x, lane = t & 31, wid = t >> 5;
    const int wm = wid & 3, wn = wid >> 2;
    const int rowbase = blockIdx.x * 128;
    const int colbase = blockIdx.y * 128;

    float c[2][8][4];
    ZERO_C(c);
    loadA_f32(As, g_S, 128, rowbase, NA, t);
    loadW(Ws, g_wcp, 256, colbase, t);
    __syncthreads();
    mma_k128(As, Ws, lane, wm, wn, c);

#pragma unroll
    for (int fm = 0; fm < 2; fm++) {
        int r0 = rowbase + wm * 32 + fm * 16 + (lane >> 2);
        float d0 = (r0 < NA) ? 2.f * g_deg[r0] : 0.f;
        float d1 = (r0 + 8 < NA) ? 2.f * g_deg[r0 + 8] : 0.f;
#pragma unroll
        for (int fn = 0; fn < 8; fn++) {
            int colp = wn * 32 + fn * 4 + (lane & 3);
            int col = colbase + colp * 2;
            float bcx = g_bc[col], bcy = g_bc[col + 1];
            float b1x = bias[col], b1y = bias[col + 1];
            int cp = (colbase >> 1) + colp;
            if (r0 < NA)
                g_h1H[(size_t)r0 * 128 + cp] =
                    packh2(fmaxf(c[fm][fn][0] + d0 * bcx + b1x, 0.f),
                           fmaxf(c[fm][fn][1] + d0 * bcy + b1y, 0.f));
            if (r0 + 8 < NA)
                g_h1H[(size_t)(r0 + 8) * 128 + cp] =
                    packh2(fmaxf(c[fm][fn][2] + d1 * bcx + b1x, 0.f),
                           fmaxf(c[fm][fn][3] + d1 * bcy + b1y, 0.f));
        }
    }
}

// ---------------------------------------------------------------------------
// mlp2: h = h1 @ W2 + b2 (K=256); relu(LN(h)) pooled atomically into out.
// ---------------------------------------------------------------------------
__global__ __launch_bounds__(256) void gemm_mlp2_pool(
    const float* __restrict__ bias,
    const float* __restrict__ ln_g, const float* __restrict__ ln_b,
    const int* __restrict__ gid, float* __restrict__ out)
{
    extern __shared__ uint32_t sm[];
    uint32_t* As = sm;
    uint32_t* Ws = sm + 128 * AS_P;
    float2* red = (float2*)Ws;
    const int t = threadIdx.x, lane = t & 31, wid = t >> 5;
    const int wm = wid & 3, wn = wid >> 2;
    const int rowbase = blockIdx.x * 128;

    float c[2][8][4];
    ZERO_C(c);
#pragma unroll
    for (int kc = 0; kc < 2; kc++) {
        if (kc) __syncthreads();
        loadA_h(As, g_h1H, 128, kc * 64, rowbase, t);
        loadW(Ws, g_w2p + (size_t)kc * 64 * 128, 128, 0, t);
        __syncthreads();
        mma_k128(As, Ws, lane, wm, wn, c);
    }

#pragma unroll
    for (int fn = 0; fn < 8; fn++) {
        int col = wn * 64 + fn * 8 + 2 * (lane & 3);
        float bx = bias[col], by = bias[col + 1];
#pragma unroll
        for (int fm = 0; fm < 2; fm++) {
            c[fm][fn][0] += bx; c[fm][fn][1] += by;
            c[fm][fn][2] += bx; c[fm][fn][3] += by;
        }
    }
    __syncthreads();
#pragma unroll
    for (int fm = 0; fm < 2; fm++) {
#pragma unroll
        for (int h = 0; h < 2; h++) {
            int row_local = wm * 32 + fm * 16 + (lane >> 2) + h * 8;
            float s = 0.f, q = 0.f;
#pragma unroll
            for (int fn = 0; fn < 8; fn++) {
                float v0 = c[fm][fn][2 * h + 0];
                float v1 = c[fm][fn][2 * h + 1];
                s += v0 + v1;
                q += v0 * v0 + v1 * v1;
            }
            s += __shfl_xor_sync(0xffffffffu, s, 1);
            q += __shfl_xor_sync(0xffffffffu, q, 1);
            s += __shfl_xor_sync(0xffffffffu, s, 2);
            q += __shfl_xor_sync(0xffffffffu, q, 2);
            if ((lane & 3) == 0) red[wn * 128 + row_local] = make_float2(s, q);
        }
    }
    __syncthreads();

#pragma unroll
    for (int fm = 0; fm < 2; fm++) {
#pragma unroll
        for (int h = 0; h < 2; h++) {
            int row_local = wm * 32 + fm * 16 + (lane >> 2) + h * 8;
            int gr = rowbase + row_local;
            if (gr >= NA) continue;
            float2 p0 = red[row_local];
            float2 p1 = red[128 + row_local];
            float mu = (p0.x + p1.x) * (1.f / 128.f);
            float var = (p0.y + p1.y) * (1.f / 128.f) - mu * mu;
            float rstd = rsqrtf(var + 1e-5f);
            int g = gid[gr];
#pragma unroll
            for (int fn = 0; fn < 8; fn++) {
                int col = wn * 64 + fn * 8 + 2 * (lane & 3);
                float v0 = c[fm][fn][2 * h + 0];
                float v1 = c[fm][fn][2 * h + 1];
                float o0 = fmaxf((v0 - mu) * rstd * ln_g[col] + ln_b[col], 0.f);
                float o1 = fmaxf((v1 - mu) * rstd * ln_g[col + 1] + ln_b[col + 1], 0.f);
                float* p = &out[(size_t)g * HD + col];
                asm volatile("red.global.add.v2.f32 [%0], {%1,%2};"
                             :: "l"(p), "f"(o0), "f"(o1) : "memory");
            }
        }
    }
}

// ---------------------------------------------------------------------------
// finalize: out[g] = (out[g] + P[g]@W + cnt*b) / max(cnt,1)
// 16384 rows = exactly 128 blocks of 128.
// ---------------------------------------------------------------------------
__global__ __launch_bounds__(256) void finalize_gemm(
    const float* __restrict__ bias, float* __restrict__ out)
{
    extern __shared__ uint32_t sm[];
    uint32_t* As = sm;
    uint32_t* Ws = sm + 128 * AS_P;
    const int t = threadIdx.x, lane = t & 31, wid = t >> 5;
    const int wm = wid & 3, wn = wid >> 2;
    const int rowbase = blockIdx.x * 128;

    float c[2][8][4];
    ZERO_C(c);
    loadA_f32(As, g_P, 128, rowbase, NG, t);
    loadW(Ws, g_wAp, 128, 0, t);
    __syncthreads();
    mma_k128(As, Ws, lane, wm, wn, c);

#pragma unroll
    for (int fm = 0; fm < 2; fm++) {
        int r0 = rowbase + wm * 32 + fm * 16 + (lane >> 2);
        int r1 = r0 + 8;
        float c0 = g_cnt[r0], c1 = g_cnt[r1];
        float i0 = 1.f / fmaxf(c0, 1.f), i1 = 1.f / fmaxf(c1, 1.f);
#pragma unroll
        for (int fn = 0; fn < 8; fn++) {
            int col = wn * 64 + fn * 8 + 2 * (lane & 3);
            float bx = bias[col], by = bias[col + 1];
            float2 h0 = *(float2*)&out[(size_t)r0 * HD + col];
            float2 h1 = *(float2*)&out[(size_t)r1 * HD + col];
            *(float2*)&out[(size_t)r0 * HD + col] =
                make_float2((h0.x + c[fm][fn][0] + c0 * bx) * i0,
                            (h0.y + c[fm][fn][1] + c0 * by) * i0);
            *(float2*)&out[(size_t)r1 * HD + col] =
                make_float2((h1.x + c[fm][fn][2] + c1 * bx) * i1,
                            (h1.y + c[fm][fn][3] + c1 * by) * i1);
        }
    }
}

// ---------------------------------------------------------------------------
extern "C" void kernel_launch(void* const* d_in, const int* in_sizes, int n_in,
                              void* d_out, int out_size)
{
    const float* node_hidden = (const float*)d_in[0];
    const float* edge_hidden = (const float*)d_in[1];
    const float* atom_w = (const float*)d_in[3];
    const float* atom_b = (const float*)d_in[4];
    const float* nmlp_w1 = (const float*)d_in[5];
    const float* nmlp_b1 = (const float*)d_in[6];
    const float* nmlp_w2 = (const float*)d_in[7];
    const float* nmlp_b2 = (const float*)d_in[8];
    const float* n_ln_g = (const float*)d_in[9];
    const float* n_ln_b = (const float*)d_in[10];
    const int* ab_src = (const int*)d_in[17];
    const int* ab_dst = (const int*)d_in[18];
    const int* node_graph_id = (const int*)d_in[21];
    float* out = (float*)d_out;

    static cudaStream_t s2 = nullptr;
    static cudaEvent_t evF = nullptr, evJ = nullptr;
    if (!s2) {
        cudaStreamCreateWithFlags(&s2, cudaStreamNonBlocking);
        cudaEventCreateWithFlags(&evF, cudaEventDisableTiming);
        cudaEventCreateWithFlags(&evJ, cudaEventDisableTiming);
        cudaFuncSetAttribute(gemm_mlp1,
            cudaFuncAttributeMaxDynamicSharedMemorySize, SM_GEMM);
        cudaFuncSetAttribute(gemm_mlp2_pool,
            cudaFuncAttributeMaxDynamicSharedMemorySize, SM_GEMM);
        cudaFuncSetAttribute(finalize_gemm,
            cudaFuncAttributeMaxDynamicSharedMemorySize, SM_GEMM);
    }

    const int NBLK = (NA + 127) / 128;

    // fork: bond scatter leg runs concurrently with prep + pooling
    cudaEventRecord(evF, 0);
    cudaStreamWaitEvent(s2, evF, 0);
    zero_S_deg<<<2048, 256, 0, s2>>>();
    scatter_raw<<<(NB + 7) / 8, 256, 0, s2>>>(node_hidden, edge_hidden,
                                              ab_src, ab_dst);
    cudaEventRecord(evJ, s2);

    // main leg
    prep_weights<<<128, 256>>>(atom_w, nmlp_w1, nmlp_w2, atom_b);
    zero_PO<<<1024, 256>>>((float4*)out);
    pool_node<<<(NA + 7) / 8, 256>>>(node_hidden, node_graph_id);

    cudaStreamWaitEvent((cudaStream_t)0, evJ, 0);   // join: mlp1 needs S, deg
    gemm_mlp1<<<dim3(NBLK, 2), 256, SM_GEMM>>>(nmlp_b1);
    gemm_mlp2_pool<<<NBLK, 256, SM_GEMM>>>(nmlp_b2, n_ln_g, n_ln_b,
                                           node_graph_id, out);
    finalize_gemm<<<NG / 128, 256, SM_GEMM>>>(atom_b, out);
}

// round 10
// speedup vs baseline: 1.9945x; 1.0303x over previous
#include <cuda_runtime.h>
#include <cuda_fp16.h>
#include <cstdint>

// ---------------------------------------------------------------------------
// DrugEncoder (angle branch dead). Full linearity restructure:
//   S[d]  = sum over bonds (node_hidden[src]+edge_hidden[b]) ; deg[d] = count
//   P[g]  = sum over atoms in g of node_hidden ; cnt[g] = atom count
//   h1    = relu(S @ Wc + 2*deg*bc + b1)   where Wc = W@W1, bc = b@W1
//   h     = h1 @ W2 + b2 ; hp[g] += relu(LN(h))      (pool atomics)
//   out[g]= (hp[g] + P[g]@W + cnt*b) / max(cnt,1)    (tiny 16384-row GEMM)
// fp16 mma m16n8k16 with ldmatrix fragment loads (A row-major smem,
// W staged n-major so B maps onto plain m8n8.x4 tiles).
// ---------------------------------------------------------------------------

#define NA 500000
#define NB 1000000
#define NG 16384
#define HD 128

__device__ float g_S[(size_t)NA * HD];
__device__ float g_deg[NA];
__device__ float g_P[(size_t)NG * HD];
__device__ float g_cnt[NG];
__device__ uint32_t g_h1H[(size_t)NA * 128];    // half2 pairs [NA][128]
__device__ uint32_t g_wAp[128 * 64];            // W   n-major [n][kpair]
__device__ uint32_t g_wcp[256 * 64];            // Wc  n-major [n][kpair]
__device__ uint32_t g_w2p[128 * 128];           // W2  n-major [n][kpair(256K)]
__device__ float g_bc[256];                     // b @ W1

// ---------------------------------------------------------------------------
__device__ __forceinline__ uint32_t packh2(float lo, float hi) {
    __half2 h = __floats2half2_rn(lo, hi);
    return *(uint32_t*)&h;
}
__device__ __forceinline__ uint32_t smem_u32(const void* p) {
    uint32_t a;
    asm("{ .reg .u64 t; cvta.to.shared.u64 t, %1; cvt.u32.u64 %0, t; }"
        : "=r"(a) : "l"(p));
    return a;
}
__device__ __forceinline__ void mma_f16(float* c, const uint32_t* a, const uint32_t* b) {
    asm volatile(
        "mma.sync.aligned.m16n8k16.row.col.f32.f16.f16.f32 "
        "{%0,%1,%2,%3}, {%4,%5,%6,%7}, {%8,%9}, {%0,%1,%2,%3};"
        : "+f"(c[0]), "+f"(c[1]), "+f"(c[2]), "+f"(c[3])
        : "r"(a[0]), "r"(a[1]), "r"(a[2]), "r"(a[3]), "r"(b[0]), "r"(b[1]));
}
__device__ __forceinline__ void ldsm4(uint32_t* r, uint32_t addr) {
    asm volatile("ldmatrix.sync.aligned.m8n8.x4.shared.b16 {%0,%1,%2,%3}, [%4];"
        : "=r"(r[0]), "=r"(r[1]), "=r"(r[2]), "=r"(r[3]) : "r"(addr));
}

#define AS_P 68      // A tile stride (words): 64 k-pairs + pad
#define WS_P 68      // W tile stride (words): 64 k-pairs + pad (n-major rows)
#define SM_GEMM ((128 * AS_P + 128 * WS_P) * 4)

#define ZERO_C(c) \
    _Pragma("unroll") for (int i = 0; i < 2; i++) \
    _Pragma("unroll") for (int j = 0; j < 8; j++) \
    _Pragma("unroll") for (int k = 0; k < 4; k++) c[i][j][k] = 0.f;

// K=128 mainloop, ldmatrix fragments; 8 warps 4m x 2n, warp tile 32x64.
__device__ __forceinline__ void mma_k128(uint32_t As_a, uint32_t Ws_a,
                                         int lane, int wm, int wn, float c[2][8][4]) {
    // A: row = wm*32 + (lane&15) (+16 for fm=1), word = ks*8 + 4*(lane>>4)
    uint32_t abase = As_a + (uint32_t)(((wm * 32 + (lane & 15)) * AS_P + (lane >> 4) * 4) * 4);
    // B: n-row = wn*64 + j*16 + (lane&7) + 8*(lane>>4), word = ks*8 + 4*((lane>>3)&1)
    uint32_t bbase = Ws_a + (uint32_t)((((wn * 64 + (lane & 7) + ((lane >> 4) & 1) * 8)) * WS_P
                                       + ((lane >> 3) & 1) * 4) * 4);
#pragma unroll
    for (int ks = 0; ks < 8; ks++) {
        uint32_t a[2][4], b[4][4];
        ldsm4(a[0], abase + ks * 32);
        ldsm4(a[1], abase + 16 * AS_P * 4 + ks * 32);
#pragma unroll
        for (int j = 0; j < 4; j++)
            ldsm4(b[j], bbase + j * 16 * WS_P * 4 + ks * 32);
#pragma unroll
        for (int fm = 0; fm < 2; fm++)
#pragma unroll
            for (int fn = 0; fn < 8; fn++) {
                uint32_t bb[2] = { b[fn >> 1][(fn & 1) * 2], b[fn >> 1][(fn & 1) * 2 + 1] };
                mma_f16(c[fm][fn], a[fm], bb);
            }
    }
}

__device__ __forceinline__ void loadA_f32(uint32_t* As, const float* __restrict__ X,
                                          int xld, int rowbase, int nrows, int t) {
#pragma unroll
    for (int p = 0; p < 16; p++) {
        int idx4 = t + p * 256;
        int r = idx4 >> 5, c4 = idx4 & 31;
        int gr = rowbase + r;
        float4 v = make_float4(0.f, 0.f, 0.f, 0.f);
        if (gr < nrows) v = *(const float4*)&X[(size_t)gr * xld + c4 * 4];
        *(uint2*)&As[r * AS_P + c4 * 2] =
            make_uint2(packh2(v.x, v.y), packh2(v.z, v.w));
    }
}

__device__ __forceinline__ void loadA_h(uint32_t* As, const uint32_t* __restrict__ Xh,
                                        int xldp, int xc0p, int rowbase, int t) {
#pragma unroll
    for (int p = 0; p < 8; p++) {
        int idx = t + p * 256;
        int r = idx >> 4, cq = idx & 15;
        int gr = rowbase + r;
        uint4 v = make_uint4(0u, 0u, 0u, 0u);
        if (gr < NA) v = *(const uint4*)&Xh[(size_t)gr * xldp + xc0p + cq * 4];
        *(uint4*)&As[r * AS_P + cq * 4] = v;
    }
}

// copy 128 n-rows x 64 kpair words of n-major W into smem
__device__ __forceinline__ void loadW_nm(uint32_t* Ws, const uint32_t* __restrict__ Wp,
                                         int row0, int wldp, int kc0, int t) {
#pragma unroll
    for (int p = 0; p < 8; p++) {
        int idx = t + p * 256;
        int r = idx >> 4, cq = idx & 15;
        *(uint4*)&Ws[r * WS_P + cq * 4] =
            *(const uint4*)&Wp[(size_t)(row0 + r) * wldp + kc0 + cq * 4];
    }
}

// ---------------------------------------------------------------------------
// prep: pack W, W2 n-major; compute Wc = W@W1 (n-major) and bc = b@W1.
// ---------------------------------------------------------------------------
__global__ void prep_weights(const float* __restrict__ wa,
                             const float* __restrict__ w1,
                             const float* __restrict__ w2,
                             const float* __restrict__ ab)
{
    int i = blockIdx.x * 256 + threadIdx.x;            // 32768 threads
    if (i < 128 * 64) {                                // W n-major
        int n = i >> 6, k2 = i & 63;
        g_wAp[i] = packh2(wa[(2 * k2) * 128 + n], wa[(2 * k2 + 1) * 128 + n]);
    }
    if (i < 128 * 128) {                               // W2 n-major
        int n = i >> 7, k2 = i & 127;
        g_w2p[i] = packh2(w2[(2 * k2) * 128 + n], w2[(2 * k2 + 1) * 128 + n]);
    }
    if (i < 256 * 64) {                                // Wc n-major
        int n = i >> 6, k2 = i & 63;
        float d0 = 0.f, d1 = 0.f;
        const float* r0 = &wa[(2 * k2) * 128];
        const float* r1 = &wa[(2 * k2 + 1) * 128];
#pragma unroll 4
        for (int j = 0; j < 128; j++) {
            float wj = w1[(size_t)j * 256 + n];
            d0 += r0[j] * wj;
            d1 += r1[j] * wj;
        }
        g_wcp[i] = packh2(d0, d1);
    }
    if (i < 256) {
        float s = 0.f;
#pragma unroll 4
        for (int j = 0; j < 128; j++) s += ab[j] * w1[(size_t)j * 256 + i];
        g_bc[i] = s;
    }
}

__global__ void zero_S_deg() {
    size_t i = (size_t)blockIdx.x * blockDim.x + threadIdx.x;
    size_t stride = (size_t)gridDim.x * blockDim.x;
    float4 z = make_float4(0.f, 0.f, 0.f, 0.f);
    float4* s4 = (float4*)g_S;
    for (size_t j = i; j < (size_t)NA * HD / 4; j += stride) s4[j] = z;
    for (size_t j = i; j < NA; j += stride) g_deg[j] = 0.f;
}

__global__ void zero_PO(float4* __restrict__ out4) {
    size_t i = (size_t)blockIdx.x * blockDim.x + threadIdx.x;
    size_t stride = (size_t)gridDim.x * blockDim.x;
    float4 z = make_float4(0.f, 0.f, 0.f, 0.f);
    for (size_t j = i; j < (size_t)NG * HD / 4; j += stride) out4[j] = z;
    float4* p4 = (float4*)g_P;
    for (size_t j = i; j < (size_t)NG * HD / 4; j += stride) p4[j] = z;
    float4* c4 = (float4*)g_cnt;
    for (size_t j = i; j < NG / 4; j += stride) c4[j] = z;
}

// ---------------------------------------------------------------------------
__global__ __launch_bounds__(256) void scatter_raw(
    const float* __restrict__ nh, const float* __restrict__ eh,
    const int* __restrict__ src, const int* __restrict__ dst)
{
    int b = blockIdx.x * 8 + (threadIdx.x >> 5);
    if (b >= NB) return;
    int lane = threadIdx.x & 31;
    int s = src[b];
    int d = dst[b];
    float4 a = *(const float4*)&nh[(size_t)s * HD + lane * 4];
    float4 e = *(const float4*)&eh[(size_t)b * HD + lane * 4];
    float4 v;
    v.x = a.x + e.x; v.y = a.y + e.y; v.z = a.z + e.z; v.w = a.w + e.w;
    float* p = &g_S[(size_t)d * HD + lane * 4];
    asm volatile("red.global.add.v4.f32 [%0], {%1,%2,%3,%4};"
                 :: "l"(p), "f"(v.x), "f"(v.y), "f"(v.z), "f"(v.w) : "memory");
    if (lane == 0) atomicAdd(&g_deg[d], 1.0f);
}

__global__ __launch_bounds__(256) void pool_node(
    const float* __restrict__ nh, const int* __restrict__ gid)
{
    int r = blockIdx.x * 8 + (threadIdx.x >> 5);
    if (r >= NA) return;
    int lane = threadIdx.x & 31;
    int g = gid[r];
    float4 v = *(const float4*)&nh[(size_t)r * HD + lane * 4];
    float* p = &g_P[(size_t)g * HD + lane * 4];
    asm volatile("red.global.add.v4.f32 [%0], {%1,%2,%3,%4};"
                 :: "l"(p), "f"(v.x), "f"(v.y), "f"(v.z), "f"(v.w) : "memory");
    if (lane == 0) atomicAdd(&g_cnt[g], 1.0f);
}

// ---------------------------------------------------------------------------
// mlp1': h1 = relu(S @ Wc + 2*deg*bc + b1), N=256 via grid.y
// ---------------------------------------------------------------------------
__global__ __launch_bounds__(256) void gemm_mlp1(const float* __restrict__ bias)
{
    extern __shared__ uint32_t sm[];
    uint32_t* As = sm;
    uint32_t* Ws = sm + 128 * AS_P;
    const uint32_t As_a = smem_u32(As), Ws_a = smem_u32(Ws);
    const int t = threadIdx.x, lane = t & 31, wid = t >> 5;
    const int wm = wid & 3, wn = wid >> 2;
    const int rowbase = blockIdx.x * 128;
    const int colbase = blockIdx.y * 128;

    float c[2][8][4];
    ZERO_C(c);
    loadA_f32(As, g_S, 128, rowbase, NA, t);
    loadW_nm(Ws, g_wcp, colbase, 64, 0, t);
    __syncthreads();
    mma_k128(As_a, Ws_a, lane, wm, wn, c);

#pragma unroll
    for (int fm = 0; fm < 2; fm++) {
        int r0 = rowbase + wm * 32 + fm * 16 + (lane >> 2);
        float d0 = (r0 < NA) ? 2.f * g_deg[r0] : 0.f;
        float d1 = (r0 + 8 < NA) ? 2.f * g_deg[r0 + 8] : 0.f;
#pragma unroll
        for (int fn = 0; fn < 8; fn++) {
            int colp = wn * 32 + fn * 4 + (lane & 3);
            int col = colbase + colp * 2;
            float bcx = g_bc[col], bcy = g_bc[col + 1];
            float b1x = bias[col], b1y = bias[col + 1];
            int cp = (colbase >> 1) + colp;
            if (r0 < NA)
                g_h1H[(size_t)r0 * 128 + cp] =
                    packh2(fmaxf(c[fm][fn][0] + d0 * bcx + b1x, 0.f),
                           fmaxf(c[fm][fn][1] + d0 * bcy + b1y, 0.f));
            if (r0 + 8 < NA)
                g_h1H[(size_t)(r0 + 8) * 128 + cp] =
                    packh2(fmaxf(c[fm][fn][2] + d1 * bcx + b1x, 0.f),
                           fmaxf(c[fm][fn][3] + d1 * bcy + b1y, 0.f));
        }
    }
}

// ---------------------------------------------------------------------------
// mlp2: h = h1 @ W2 + b2 (K=256); relu(LN(h)) pooled atomically into out.
// ---------------------------------------------------------------------------
__global__ __launch_bounds__(256) void gemm_mlp2_pool(
    const float* __restrict__ bias,
    const float* __restrict__ ln_g, const float* __restrict__ ln_b,
    const int* __restrict__ gid, float* __restrict__ out)
{
    extern __shared__ uint32_t sm[];
    uint32_t* As = sm;
    uint32_t* Ws = sm + 128 * AS_P;
    const uint32_t As_a = smem_u32(As), Ws_a = smem_u32(Ws);
    float2* red = (float2*)Ws;
    const int t = threadIdx.x, lane = t & 31, wid = t >> 5;
    const int wm = wid & 3, wn = wid >> 2;
    const int rowbase = blockIdx.x * 128;

    float c[2][8][4];
    ZERO_C(c);
#pragma unroll
    for (int kc = 0; kc < 2; kc++) {
        if (kc) __syncthreads();
        loadA_h(As, g_h1H, 128, kc * 64, rowbase, t);
        loadW_nm(Ws, g_w2p, 0, 128, kc * 64, t);
        __syncthreads();
        mma_k128(As_a, Ws_a, lane, wm, wn, c);
    }

#pragma unroll
    for (int fn = 0; fn < 8; fn++) {
        int col = wn * 64 + fn * 8 + 2 * (lane & 3);
        float bx = bias[col], by = bias[col + 1];
#pragma unroll
        for (int fm = 0; fm < 2; fm++) {
            c[fm][fn][0] += bx; c[fm][fn][1] += by;
            c[fm][fn][2] += bx; c[fm][fn][3] += by;
        }
    }
    __syncthreads();
#pragma unroll
    for (int fm = 0; fm < 2; fm++) {
#pragma unroll
        for (int h = 0; h < 2; h++) {
            int row_local = wm * 32 + fm * 16 + (lane >> 2) + h * 8;
            float s = 0.f, q = 0.f;
#pragma unroll
            for (int fn = 0; fn < 8; fn++) {
                float v0 = c[fm][fn][2 * h + 0];
                float v1 = c[fm][fn][2 * h + 1];
                s += v0 + v1;
                q += v0 * v0 + v1 * v1;
            }
            s += __shfl_xor_sync(0xffffffffu, s, 1);
            q += __shfl_xor_sync(0xffffffffu, q, 1);
            s += __shfl_xor_sync(0xffffffffu, s, 2);
            q += __shfl_xor_sync(0xffffffffu, q, 2);
            if ((lane & 3) == 0) red[wn * 128 + row_local] = make_float2(s, q);
        }
    }
    __syncthreads();

#pragma unroll
    for (int fm = 0; fm < 2; fm++) {
#pragma unroll
        for (int h = 0; h < 2; h++) {
            int row_local = wm * 32 + fm * 16 + (lane >> 2) + h * 8;
            int gr = rowbase + row_local;
            if (gr >= NA) continue;
            float2 p0 = red[row_local];
            float2 p1 = red[128 + row_local];
            float mu = (p0.x + p1.x) * (1.f / 128.f);
            float var = (p0.y + p1.y) * (1.f / 128.f) - mu * mu;
            float rstd = rsqrtf(var + 1e-5f);
            int g = gid[gr];
#pragma unroll
            for (int fn = 0; fn < 8; fn++) {
                int col = wn * 64 + fn * 8 + 2 * (lane & 3);
                float v0 = c[fm][fn][2 * h + 0];
                float v1 = c[fm][fn][2 * h + 1];
                float o0 = fmaxf((v0 - mu) * rstd * ln_g[col] + ln_b[col], 0.f);
                float o1 = fmaxf((v1 - mu) * rstd * ln_g[col + 1] + ln_b[col + 1], 0.f);
                float* p = &out[(size_t)g * HD + col];
                asm volatile("red.global.add.v2.f32 [%0], {%1,%2};"
                             :: "l"(p), "f"(o0), "f"(o1) : "memory");
            }
        }
    }
}

// ---------------------------------------------------------------------------
// finalize: out[g] = (out[g] + P[g]@W + cnt*b) / max(cnt,1)
// ---------------------------------------------------------------------------
__global__ __launch_bounds__(256) void finalize_gemm(
    const float* __restrict__ bias, float* __restrict__ out)
{
    extern __shared__ uint32_t sm[];
    uint32_t* As = sm;
    uint32_t* Ws = sm + 128 * AS_P;
    const uint32_t As_a = smem_u32(As), Ws_a = smem_u32(Ws);
    const int t = threadIdx.x, lane = t & 31, wid = t >> 5;
    const int wm = wid & 3, wn = wid >> 2;
    const int rowbase = blockIdx.x * 128;

    float c[2][8][4];
    ZERO_C(c);
    loadA_f32(As, g_P, 128, rowbase, NG, t);
    loadW_nm(Ws, g_wAp, 0, 64, 0, t);
    __syncthreads();
    mma_k128(As_a, Ws_a, lane, wm, wn, c);

#pragma unroll
    for (int fm = 0; fm < 2; fm++) {
        int r0 = rowbase + wm * 32 + fm * 16 + (lane >> 2);
        int r1 = r0 + 8;
        float c0 = g_cnt[r0], c1 = g_cnt[r1];
        float i0 = 1.f / fmaxf(c0, 1.f), i1 = 1.f / fmaxf(c1, 1.f);
#pragma unroll
        for (int fn = 0; fn < 8; fn++) {
            int col = wn * 64 + fn * 8 + 2 * (lane & 3);
            float bx = bias[col], by = bias[col + 1];
            float2 h0 = *(float2*)&out[(size_t)r0 * HD + col];
            float2 h1 = *(float2*)&out[(size_t)r1 * HD + col];
            *(float2*)&out[(size_t)r0 * HD + col] =
                make_float2((h0.x + c[fm][fn][0] + c0 * bx) * i0,
                            (h0.y + c[fm][fn][1] + c0 * by) * i0);
            *(float2*)&out[(size_t)r1 * HD + col] =
                make_float2((h1.x + c[fm][fn][2] + c1 * bx) * i1,
                            (h1.y + c[fm][fn][3] + c1 * by) * i1);
        }
    }
}

// ---------------------------------------------------------------------------
extern "C" void kernel_launch(void* const* d_in, const int* in_sizes, int n_in,
                              void* d_out, int out_size)
{
    const float* node_hidden = (const float*)d_in[0];
    const float* edge_hidden = (const float*)d_in[1];
    const float* atom_w = (const float*)d_in[3];
    const float* atom_b = (const float*)d_in[4];
    const float* nmlp_w1 = (const float*)d_in[5];
    const float* nmlp_b1 = (const float*)d_in[6];
    const float* nmlp_w2 = (const float*)d_in[7];
    const float* nmlp_b2 = (const float*)d_in[8];
    const float* n_ln_g = (const float*)d_in[9];
    const float* n_ln_b = (const float*)d_in[10];
    const int* ab_src = (const int*)d_in[17];
    const int* ab_dst = (const int*)d_in[18];
    const int* node_graph_id = (const int*)d_in[21];
    float* out = (float*)d_out;

    static cudaStream_t s2 = nullptr;
    static cudaEvent_t evF = nullptr, evJ = nullptr;
    if (!s2) {
        cudaStreamCreateWithFlags(&s2, cudaStreamNonBlocking);
        cudaEventCreateWithFlags(&evF, cudaEventDisableTiming);
        cudaEventCreateWithFlags(&evJ, cudaEventDisableTiming);
        cudaFuncSetAttribute(gemm_mlp1,
            cudaFuncAttributeMaxDynamicSharedMemorySize, SM_GEMM);
        cudaFuncSetAttribute(gemm_mlp2_pool,
            cudaFuncAttributeMaxDynamicSharedMemorySize, SM_GEMM);
        cudaFuncSetAttribute(finalize_gemm,
            cudaFuncAttributeMaxDynamicSharedMemorySize, SM_GEMM);
    }

    const int NBLK = (NA + 127) / 128;

    // fork: bond scatter leg runs concurrently with prep + pooling
    cudaEventRecord(evF, 0);
    cudaStreamWaitEvent(s2, evF, 0);
    zero_S_deg<<<2048, 256, 0, s2>>>();
    scatter_raw<<<(NB + 7) / 8, 256, 0, s2>>>(node_hidden, edge_hidden,
                                              ab_src, ab_dst);
    cudaEventRecord(evJ, s2);

    // main leg
    prep_weights<<<128, 256>>>(atom_w, nmlp_w1, nmlp_w2, atom_b);
    zero_PO<<<1024, 256>>>((float4*)out);
    pool_node<<<(NA + 7) / 8, 256>>>(node_hidden, node_graph_id);

    cudaStreamWaitEvent((cudaStream_t)0, evJ, 0);   // join: mlp1 needs S, deg
    gemm_mlp1<<<dim3(NBLK, 2), 256, SM_GEMM>>>(nmlp_b1);
    gemm_mlp2_pool<<<NBLK, 256, SM_GEMM>>>(nmlp_b2, n_ln_g, n_ln_b,
                                           node_graph_id, out);
    finalize_gemm<<<NG / 128, 256, SM_GEMM>>>(atom_b, out);
}